// round 9
// baseline (speedup 1.0000x reference)
#include <cuda_runtime.h>
#include <cuda_bf16.h>
#include <math.h>
#include <stdint.h>

// Problem constants
#define BB 4
#define HH 128
#define WW 128
#define CC 512
#define NTOK 16384            // H*W
#define NHEAD 8
#define DHEAD 64
#define MTOT (BB*NTOK)        // 65536
#define GSPLIT 8
#define GS_TOT 64

typedef __nv_bfloat16 bf16;

// ---------------- scratch (device globals; no runtime allocation) ----------
static __device__ float g_vinp[(size_t)MTOT * CC];   // raw x@Wv (conv branch)
static __device__ float g_weff[(size_t)BB * CC * CC];

static __device__ __align__(16) bf16 g_xhi[(size_t)MTOT * CC];
static __device__ __align__(16) bf16 g_xlo[(size_t)MTOT * CC];
static __device__ __align__(16) bf16 g_vhi[(size_t)MTOT * CC];
static __device__ __align__(16) bf16 g_vlo[(size_t)MTOT * CC];
static __device__ __align__(16) bf16 g_wThi[3 * CC * CC];
static __device__ __align__(16) bf16 g_wTlo[3 * CC * CC];
static __device__ __align__(16) bf16 g_wfhi[(size_t)BB * CC * CC];
static __device__ __align__(16) bf16 g_wflo[(size_t)BB * CC * CC];
static __device__ __align__(16) bf16 g_qthi[(size_t)BB * CC * NTOK];
static __device__ __align__(16) bf16 g_qtlo[(size_t)BB * CC * NTOK];
static __device__ __align__(16) bf16 g_kthi[(size_t)BB * CC * NTOK];
static __device__ __align__(16) bf16 g_ktlo[(size_t)BB * CC * NTOK];

static __device__ float g_invq[BB * CC];
static __device__ float g_invk[BB * CC];
static __device__ float g_gpart[(size_t)GS_TOT * BB * NHEAD * DHEAD * DHEAD];
static __device__ float g_attn[(size_t)BB * NHEAD * DHEAD * DHEAD];

// =================== helpers ==============================================
__device__ __forceinline__ uint32_t s2u(const void* p) {
    uint32_t a;
    asm("{ .reg .u64 t; cvta.to.shared.u64 t, %1; cvt.u32.u64 %0, t; }"
        : "=r"(a) : "l"(p));
    return a;
}

// split 2 floats -> packed bf16 hi pair and lo pair (low half = first arg)
__device__ __forceinline__ void cvt2(float a, float b, uint32_t& h, uint32_t& l) {
    uint32_t hp;
    asm("cvt.rn.bf16x2.f32 %0, %1, %2;" : "=r"(hp) : "f"(b), "f"(a));
    float ah = __uint_as_float(hp << 16);
    float bh = __uint_as_float(hp & 0xFFFF0000u);
    float al = a - ah;
    float bl = b - bh;
    uint32_t lp;
    asm("cvt.rn.bf16x2.f32 %0, %1, %2;" : "=r"(lp) : "f"(bl), "f"(al));
    h = hp; l = lp;
}

__device__ __forceinline__ void split1(float f, uint16_t& h, uint16_t& l) {
    uint32_t hp;
    asm("cvt.rn.bf16x2.f32 %0, %1, %2;" : "=r"(hp) : "f"(0.f), "f"(f));
    float hf = __uint_as_float(hp << 16);
    float lf = f - hf;
    uint32_t lp;
    asm("cvt.rn.bf16x2.f32 %0, %1, %2;" : "=r"(lp) : "f"(0.f), "f"(lf));
    h = (uint16_t)hp; l = (uint16_t)lp;
}

__device__ __forceinline__ float bfu16_to_f(uint32_t u) {
    return __uint_as_float(u << 16);
}

__device__ __forceinline__ void ldm_x4(uint32_t* r, uint32_t addr) {
    asm volatile("ldmatrix.sync.aligned.m8n8.x4.shared.b16 {%0,%1,%2,%3}, [%4];"
                 : "=r"(r[0]), "=r"(r[1]), "=r"(r[2]), "=r"(r[3]) : "r"(addr));
}
__device__ __forceinline__ void mma16816(float* c, const uint32_t* a, const uint32_t* b) {
    asm volatile(
        "mma.sync.aligned.m16n8k16.row.col.f32.bf16.bf16.f32 "
        "{%0,%1,%2,%3}, {%4,%5,%6,%7}, {%8,%9}, {%0,%1,%2,%3};"
        : "+f"(c[0]), "+f"(c[1]), "+f"(c[2]), "+f"(c[3])
        : "r"(a[0]), "r"(a[1]), "r"(a[2]), "r"(a[3]), "r"(b[0]), "r"(b[1]));
}
__device__ __forceinline__ void cp16(uint32_t dst, const void* src) {
    asm volatile("cp.async.cg.shared.global [%0], [%1], 16;" :: "r"(dst), "l"(src));
}

// =================== conversion kernels ====================================
__global__ void cvt_x(const float* __restrict__ x, bf16* __restrict__ xhi,
                      bf16* __restrict__ xlo)
{
    size_t g = ((size_t)blockIdx.x * 256 + threadIdx.x);
    const float4* p = (const float4*)(x + g * 8);
    float4 a = p[0], b = p[1];
    uint4 h, l;
    cvt2(a.x, a.y, h.x, l.x); cvt2(a.z, a.w, h.y, l.y);
    cvt2(b.x, b.y, h.z, l.z); cvt2(b.z, b.w, h.w, l.w);
    ((uint4*)xhi)[g] = h;
    ((uint4*)xlo)[g] = l;
}

// transpose + convert: src fp32 [R][512] (batched) -> dst bf16 [512][R] hi/lo
__global__ void tcvt(const float* __restrict__ src, bf16* __restrict__ dhi,
                     bf16* __restrict__ dlo, int R, size_t sStride, size_t dStride)
{
    __shared__ uint16_t shh[32][65];
    __shared__ uint16_t shl[32][65];
    int z = blockIdx.z;
    const float* s = src + (size_t)z * sStride;
    int c = blockIdx.y * 32 + threadIdx.x;
    int nb = blockIdx.x * 64;
#pragma unroll
    for (int i = 0; i < 8; i++) {
        int n = threadIdx.y + i * 8;
        float f = s[(size_t)(nb + n) * CC + c];
        uint16_t h, l;
        split1(f, h, l);
        shh[threadIdx.x][n] = h;
        shl[threadIdx.x][n] = l;
    }
    __syncthreads();
#pragma unroll
    for (int i = 0; i < 4; i++) {
        int cl = threadIdx.y + i * 8;
        int row = blockIdx.y * 32 + cl;
        size_t u32idx = ((size_t)row * R + nb) >> 1;
        uint32_t h = (uint32_t)shh[cl][threadIdx.x * 2] |
                     ((uint32_t)shh[cl][threadIdx.x * 2 + 1] << 16);
        uint32_t l = (uint32_t)shl[cl][threadIdx.x * 2] |
                     ((uint32_t)shl[cl][threadIdx.x * 2 + 1] << 16);
        ((uint32_t*)(dhi + (size_t)z * dStride))[u32idx + threadIdx.x] = h;
        ((uint32_t*)(dlo + (size_t)z * dStride))[u32idx + threadIdx.x] = l;
    }
}

// =================== pipelined bf16 GEMM, CTA 128x128, 4 warps 64x64 =======
// C[M,512] = A[M,512] @ Bt[512,512]^T, operands bf16 hi/lo (3-term split).
// 4 warps (2x2), warp tile 64x64, k-chunk 32, 2-stage cp.async, 2 CTAs/SM.
// MODE 1: C2 = raw fp32; Vhi/Vlo = bf16 split of raw*illu
// MODE 2: C = A@B + bias
// MODE 3: transposed bf16 hi/lo output Oh/Ol[b][col][row] (for q,k)
#define KCH 32
#define ROWB 80
#define MATB (128 * ROWB)        // 10240
#define STAGEB (4 * MATB)        // 40960
#define GEMM_SMEM (2 * STAGEB)   // 81920

__device__ __forceinline__ void stage_issue(
    uint32_t sb, int tid,
    const bf16* aHi, const bf16* aLo, const bf16* bHi, const bf16* bLo)
{
    const bf16* g[4] = {aHi, aLo, bHi, bLo};
#pragma unroll
    for (int m = 0; m < 4; m++) {
#pragma unroll
        for (int it = 0; it < 4; it++) {
            int u = tid + it * 128;
            int r = u >> 2, seg = u & 3;
            cp16(sb + m * MATB + r * ROWB + seg * 16,
                 g[m] + (size_t)r * CC + seg * 8);
        }
    }
    asm volatile("cp.async.commit_group;" ::: "memory");
}

template <int MODE>
__global__ void __launch_bounds__(128, 2) gemm_bf(
    const bf16* __restrict__ Ahi, const bf16* __restrict__ Alo,
    const bf16* __restrict__ Bhi, const bf16* __restrict__ Blo,
    float* __restrict__ C, float* __restrict__ C2,
    bf16* __restrict__ Vhi, bf16* __restrict__ Vlo,
    const float* __restrict__ illu, const float* __restrict__ bias,
    size_t zRow, size_t sB)
{
    extern __shared__ char smem[];
    const uint32_t sb0 = s2u(smem);
    const int tid = threadIdx.x;
    const int wid = tid >> 5, lane = tid & 31;
    const int wm = wid & 1, wn = wid >> 1;     // 2x2 warps

    const size_t row0 = (size_t)blockIdx.y * 128 + (size_t)blockIdx.z * zRow;
    const int n0 = blockIdx.x * 128;
    const size_t boff = (size_t)blockIdx.z * sB + (size_t)n0 * CC;

    float acc[4][8][4];
#pragma unroll
    for (int i = 0; i < 4; i++)
#pragma unroll
        for (int j = 0; j < 8; j++)
#pragma unroll
            for (int t = 0; t < 4; t++) acc[i][j][t] = 0.f;

    const int a_row = wm * 64 + (lane & 15);
    const int a_koff = (lane >> 4) * 16;
    const int b_row4 = wn * 64 + ((lane >> 4) & 1) * 8 + (lane & 7);
    const int b_koff4 = ((lane >> 3) & 1) * 16;

    stage_issue(sb0, tid, Ahi + row0 * CC, Alo + row0 * CC, Bhi + boff, Blo + boff);
    stage_issue(sb0 + STAGEB, tid, Ahi + row0 * CC + KCH, Alo + row0 * CC + KCH,
                Bhi + boff + KCH, Blo + boff + KCH);

    for (int ch = 0; ch < 16; ch++) {
        const int cur = ch & 1;
        if (ch < 15) asm volatile("cp.async.wait_group 1;" ::: "memory");
        else         asm volatile("cp.async.wait_group 0;" ::: "memory");
        __syncthreads();

        const uint32_t base = sb0 + cur * STAGEB;
        const uint32_t aHs = base, aLs = base + MATB;
        const uint32_t bHs = base + 2 * MATB, bLs = base + 3 * MATB;
#pragma unroll
        for (int ks = 0; ks < 2; ks++) {
            const int kb = ks * 32;
            uint32_t ah[4][4], al[4][4];
#pragma unroll
            for (int i = 0; i < 4; i++) {
                uint32_t ra = (a_row + i * 16) * ROWB + kb + a_koff;
                ldm_x4(ah[i], aHs + ra);
                ldm_x4(al[i], aLs + ra);
            }
#pragma unroll
            for (int jp = 0; jp < 4; jp++) {
                uint32_t rb = (b_row4 + jp * 16) * ROWB + kb + b_koff4;
                uint32_t th[4], tl[4];
                ldm_x4(th, bHs + rb);
                ldm_x4(tl, bLs + rb);
#pragma unroll
                for (int i = 0; i < 4; i++) {
                    mma16816(acc[i][jp * 2], ah[i], th);
                    mma16816(acc[i][jp * 2], ah[i], tl);
                    mma16816(acc[i][jp * 2], al[i], th);
                    mma16816(acc[i][jp * 2 + 1], ah[i], th + 2);
                    mma16816(acc[i][jp * 2 + 1], ah[i], tl + 2);
                    mma16816(acc[i][jp * 2 + 1], al[i], th + 2);
                }
            }
        }
        __syncthreads();
        if (ch + 2 < 16) {
            const int k0 = (ch + 2) * KCH;
            stage_issue(base, tid, Ahi + row0 * CC + k0, Alo + row0 * CC + k0,
                        Bhi + boff + k0, Blo + boff + k0);
        }
    }

    // ---- epilogue ----
    const int mrow = wm * 64 + (lane >> 2);
    const int mcol = wn * 64 + (lane & 3) * 2;

    if (MODE == 3) {
        // transposed bf16 hi/lo output via smem transpose (128 cols x 128 rows)
        uint16_t* shh = (uint16_t*)smem;              // [128 cols][130]
        uint16_t* shl = shh + 128 * 130;
        __syncthreads();
#pragma unroll
        for (int i = 0; i < 4; i++)
#pragma unroll
            for (int half = 0; half < 2; half++) {
                int row = mrow + i * 16 + half * 8;
#pragma unroll
                for (int j = 0; j < 8; j++) {
                    int col = mcol + j * 8;
                    uint32_t h, l;
                    cvt2(acc[i][j][half * 2 + 0], acc[i][j][half * 2 + 1], h, l);
                    shh[col * 130 + row] = (uint16_t)h;
                    shh[(col + 1) * 130 + row] = (uint16_t)(h >> 16);
                    shl[col * 130 + row] = (uint16_t)l;
                    shl[(col + 1) * 130 + row] = (uint16_t)(l >> 16);
                }
            }
        __syncthreads();
        const int b = (int)(blockIdx.y >> 7);
        const size_t nl0 = (size_t)(blockIdx.y & 127) * 128;
        uint32_t* dh = (uint32_t*)Vhi;
        uint32_t* dl = (uint32_t*)Vlo;
#pragma unroll
        for (int it = 0; it < 64; it++) {
            int c = it * 2 + (tid >> 6);
            int w = tid & 63;
            uint32_t hv = *(uint32_t*)(&shh[c * 130 + 2 * w]);
            uint32_t lv = *(uint32_t*)(&shl[c * 130 + 2 * w]);
            size_t idx = ((((size_t)b * CC + n0 + c) * NTOK + nl0) >> 1) + w;
            dh[idx] = hv;
            dl[idx] = lv;
        }
        return;
    }

#pragma unroll
    for (int i = 0; i < 4; i++) {
#pragma unroll
        for (int half = 0; half < 2; half++) {
            size_t r = row0 + mrow + i * 16 + half * 8;
            size_t base = r * CC + n0 + mcol;
#pragma unroll
            for (int j = 0; j < 8; j++) {
                float2 v2;
                v2.x = acc[i][j][half * 2 + 0];
                v2.y = acc[i][j][half * 2 + 1];
                size_t off = base + j * 8;
                if (MODE == 1) {
                    float2 iv = *(const float2*)(illu + off);
                    *(float2*)(C2 + off) = v2;
                    uint32_t h, l;
                    cvt2(v2.x * iv.x, v2.y * iv.y, h, l);
                    ((uint32_t*)Vhi)[off >> 1] = h;
                    ((uint32_t*)Vlo)[off >> 1] = l;
                } else {
                    float2 bv = *(const float2*)(bias + n0 + mcol + j * 8);
                    v2.x += bv.x; v2.y += bv.y;
                    *(float2*)(C + off) = v2;
                }
            }
        }
    }
}

// ------------- norms from transposed bf16 hi/lo (contiguous rows) ----------
__global__ void normsq_t(const bf16* __restrict__ qh_, const bf16* __restrict__ ql_,
                         const bf16* __restrict__ kh_, const bf16* __restrict__ kl_,
                         float* __restrict__ iq, float* __restrict__ ik)
{
    const int c = blockIdx.x, b = blockIdx.y;
    const int tid = threadIdx.x;
    const size_t b32 = (((size_t)b * CC + c) * NTOK) >> 1;
    const uint32_t* qh = (const uint32_t*)qh_ + b32;
    const uint32_t* ql = (const uint32_t*)ql_ + b32;
    const uint32_t* kh = (const uint32_t*)kh_ + b32;
    const uint32_t* kl = (const uint32_t*)kl_ + b32;

    float sq = 0.f, sk = 0.f;
    for (int i = tid; i < NTOK / 2; i += 256) {
        uint32_t h = qh[i], l = ql[i];
        float f0 = bfu16_to_f(h & 0xFFFF) + bfu16_to_f(l & 0xFFFF);
        float f1 = bfu16_to_f(h >> 16) + bfu16_to_f(l >> 16);
        sq += f0 * f0 + f1 * f1;
        h = kh[i]; l = kl[i];
        f0 = bfu16_to_f(h & 0xFFFF) + bfu16_to_f(l & 0xFFFF);
        f1 = bfu16_to_f(h >> 16) + bfu16_to_f(l >> 16);
        sk += f0 * f0 + f1 * f1;
    }
    __shared__ float red[2][256];
    red[0][tid] = sq; red[1][tid] = sk;
    __syncthreads();
    for (int s = 128; s > 0; s >>= 1) {
        if (tid < s) {
            red[0][tid] += red[0][tid + s];
            red[1][tid] += red[1][tid + s];
        }
        __syncthreads();
    }
    if (tid == 0) {
        iq[b * CC + c] = 1.f / fmaxf(sqrtf(red[0][0]), 1e-12f);
        ik[b * CC + c] = 1.f / fmaxf(sqrtf(red[1][0]), 1e-12f);
    }
}

// ------------- Gram via mma with direct-LDG fragments ----------------------
__global__ void __launch_bounds__(256) gram_mma(
    const bf16* __restrict__ KThi, const bf16* __restrict__ KTlo,
    const bf16* __restrict__ QThi, const bf16* __restrict__ QTlo,
    float* __restrict__ part)
{
    const int h = blockIdx.x, b = blockIdx.y, s = blockIdx.z;
    const int wid = threadIdx.x >> 5, lane = threadIdx.x & 31;
    const int nbase = s * (NTOK / GSPLIT) + wid * 256;

    const size_t rowbase = ((size_t)b * CC + h * DHEAD) * NTOK;
    const bf16* Kh = KThi + rowbase;
    const bf16* Kl = KTlo + rowbase;
    const bf16* Qh = QThi + rowbase;
    const bf16* Ql = QTlo + rowbase;

    float acc[4][8][4];
#pragma unroll
    for (int i = 0; i < 4; i++)
#pragma unroll
        for (int j = 0; j < 8; j++)
#pragma unroll
            for (int t = 0; t < 4; t++) acc[i][j][t] = 0.f;

    const int rsel = lane >> 2;
    const int csel = (lane & 3) * 2;

    for (int step = 0; step < 16; step++) {
        const int nb = nbase + step * 16 + csel;
        uint32_t ah[4][4], al[4][4];
#pragma unroll
        for (int mt = 0; mt < 4; mt++) {
            const size_t r0 = (size_t)(mt * 16 + rsel) * NTOK;
            const size_t r8 = r0 + 8 * NTOK;
            ah[mt][0] = *(const uint32_t*)(Kh + r0 + nb);
            ah[mt][1] = *(const uint32_t*)(Kh + r8 + nb);
            ah[mt][2] = *(const uint32_t*)(Kh + r0 + nb + 8);
            ah[mt][3] = *(const uint32_t*)(Kh + r8 + nb + 8);
            al[mt][0] = *(const uint32_t*)(Kl + r0 + nb);
            al[mt][1] = *(const uint32_t*)(Kl + r8 + nb);
            al[mt][2] = *(const uint32_t*)(Kl + r0 + nb + 8);
            al[mt][3] = *(const uint32_t*)(Kl + r8 + nb + 8);
        }
#pragma unroll
        for (int nt = 0; nt < 8; nt++) {
            const size_t q0 = (size_t)(nt * 8 + rsel) * NTOK;
            uint32_t bh[2], bl[2];
            bh[0] = *(const uint32_t*)(Qh + q0 + nb);
            bh[1] = *(const uint32_t*)(Qh + q0 + nb + 8);
            bl[0] = *(const uint32_t*)(Ql + q0 + nb);
            bl[1] = *(const uint32_t*)(Ql + q0 + nb + 8);
#pragma unroll
            for (int mt = 0; mt < 4; mt++) {
                mma16816(acc[mt][nt], ah[mt], bh);
                mma16816(acc[mt][nt], ah[mt], bl);
                mma16816(acc[mt][nt], al[mt], bh);
            }
        }
    }

    const int sp = s * 8 + wid;
    float* dst = part + (((size_t)sp * BB + b) * NHEAD + h) * 4096;
#pragma unroll
    for (int mt = 0; mt < 4; mt++)
#pragma unroll
        for (int nt = 0; nt < 8; nt++) {
            int r = mt * 16 + rsel, c = nt * 8 + csel;
            dst[r * 64 + c]           = acc[mt][nt][0];
            dst[r * 64 + c + 1]       = acc[mt][nt][1];
            dst[(r + 8) * 64 + c]     = acc[mt][nt][2];
            dst[(r + 8) * 64 + c + 1] = acc[mt][nt][3];
        }
}

// ------------- softmax over e ----------------------------------------------
__global__ void softmax_kernel(const float* __restrict__ part,
                               const float* __restrict__ iq,
                               const float* __restrict__ ik,
                               const float* __restrict__ rescale,
                               float* __restrict__ attn)
{
    int bh = blockIdx.x;
    int b = bh / NHEAD, h = bh % NHEAD;
    int d = threadIdx.x;

    __shared__ float iq_s[64];
    iq_s[d] = iq[b * CC + h * DHEAD + d];
    float ik_d = ik[b * CC + h * DHEAD + d];
    float resc = rescale[h];
    __syncthreads();

    float row[64];
#pragma unroll
    for (int e = 0; e < 64; e++) row[e] = 0.f;
    for (int sp = 0; sp < GS_TOT; sp++) {
        const float* p = part + (((size_t)sp * BB + b) * NHEAD + h) * 4096 + d * 64;
#pragma unroll 8
        for (int e = 0; e < 64; e++) row[e] += p[e];
    }
    float m = -1e30f;
#pragma unroll
    for (int e = 0; e < 64; e++) {
        row[e] = row[e] * ik_d * iq_s[e] * resc;
        m = fmaxf(m, row[e]);
    }
    float sum = 0.f;
#pragma unroll
    for (int e = 0; e < 64; e++) {
        row[e] = __expf(row[e] - m);
        sum += row[e];
    }
    float inv = 1.f / sum;
    float* dst = attn + ((size_t)(b * NHEAD + h)) * 4096 + d * 64;
#pragma unroll
    for (int e = 0; e < 64; e++) dst[e] = row[e] * inv;
}

// ------------- Weff[b][h*64+e][j] = sum_d attn[b,h,d,e] * Wp[h*64+d][j] -----
__global__ void weff_kernel(const float* __restrict__ attn,
                            const float* __restrict__ Wp,
                            float* __restrict__ weff)
{
    int eg = blockIdx.x;
    int b = blockIdx.y;
    int tid = threadIdx.x;
    int h = eg >> 6, e = eg & 63;

    __shared__ float a_s[64];
    if (tid < 64) a_s[tid] = attn[((size_t)(b * NHEAD + h) * 64 + tid) * 64 + e];
    __syncthreads();

    for (int j = tid; j < CC; j += 256) {
        float acc = 0.f;
#pragma unroll
        for (int d = 0; d < 64; d++)
            acc += a_s[d] * Wp[(size_t)(h * 64 + d) * CC + j];
        weff[((size_t)b * CC + eg) * CC + j] = acc;
    }
}

// ------------- fused dwconv3 -> GELU -> dwconv3 (NHWC), SAME padding -------
__global__ void __launch_bounds__(256) dwconv_fused(
    const float* __restrict__ in, const float* __restrict__ w1,
    const float* __restrict__ w2, float* __restrict__ out)
{
    __shared__ float t[18 * 18 * 32];
    const int chb = (blockIdx.z & 15) * 32;
    const int b = blockIdx.z >> 4;
    const int x0 = blockIdx.x * 16, y0 = blockIdx.y * 16;
    const int ch = threadIdx.x & 31;
    const int sp = threadIdx.x >> 5;

    float wv[9];
#pragma unroll
    for (int k = 0; k < 9; k++) wv[k] = w1[(chb + ch) * 9 + k];

    for (int p = sp; p < 324; p += 8) {
        int ly = p / 18, lx = p - ly * 18;
        int gy = y0 + ly - 1, gx = x0 + lx - 1;
        float val = 0.f;
        if (gy >= 0 && gy < HH && gx >= 0 && gx < WW) {
            float acc = 0.f;
#pragma unroll
            for (int dy = -1; dy <= 1; dy++) {
                int yy = gy + dy;
                if (yy < 0 || yy > HH - 1) continue;
#pragma unroll
                for (int dx = -1; dx <= 1; dx++) {
                    int xx = gx + dx;
                    if (xx < 0 || xx > WW - 1) continue;
                    acc += in[(((size_t)b * HH + yy) * WW + xx) * CC + chb + ch] *
                           wv[(dy + 1) * 3 + (dx + 1)];
                }
            }
            val = 0.5f * acc * (1.f + erff(acc * 0.70710678118654752f));
        }
        t[p * 32 + ch] = val;
    }
    __syncthreads();

#pragma unroll
    for (int k = 0; k < 9; k++) wv[k] = w2[(chb + ch) * 9 + k];

    for (int p = sp; p < 256; p += 8) {
        int ly = p >> 4, lx = p & 15;
        float acc = 0.f;
#pragma unroll
        for (int dy = 0; dy < 3; dy++)
#pragma unroll
            for (int dx = 0; dx < 3; dx++)
                acc += t[((ly + dy) * 18 + lx + dx) * 32 + ch] * wv[dy * 3 + dx];
        size_t o = (((size_t)b * HH + y0 + ly) * WW + x0 + lx) * CC + chb + ch;
        out[o] += acc;
    }
}

// ---------------------------------------------------------------------------
extern "C" void kernel_launch(void* const* d_in, const int* in_sizes, int n_in,
                              void* d_out, int out_size)
{
    const float* x    = (const float*)d_in[0];
    const float* illu = (const float*)d_in[1];
    const float* Wq   = (const float*)d_in[2];
    const float* Wk   = (const float*)d_in[3];
    const float* Wv   = (const float*)d_in[4];
    const float* resc = (const float*)d_in[5];
    const float* Wp   = (const float*)d_in[6];
    const float* bp   = (const float*)d_in[7];
    const float* c1w  = (const float*)d_in[8];
    const float* c2w  = (const float*)d_in[9];
    float* out = (float*)d_out;

    float *vinp, *weff, *iq, *ik, *gp, *attn;
    bf16 *xhi, *xlo, *vhi, *vlo, *wThi, *wTlo, *wfhi, *wflo;
    bf16 *qthi, *qtlo, *kthi, *ktlo;
    cudaGetSymbolAddress((void**)&vinp, g_vinp);
    cudaGetSymbolAddress((void**)&weff, g_weff);
    cudaGetSymbolAddress((void**)&iq, g_invq);
    cudaGetSymbolAddress((void**)&ik, g_invk);
    cudaGetSymbolAddress((void**)&gp, g_gpart);
    cudaGetSymbolAddress((void**)&attn, g_attn);
    cudaGetSymbolAddress((void**)&xhi, g_xhi);
    cudaGetSymbolAddress((void**)&xlo, g_xlo);
    cudaGetSymbolAddress((void**)&vhi, g_vhi);
    cudaGetSymbolAddress((void**)&vlo, g_vlo);
    cudaGetSymbolAddress((void**)&wThi, g_wThi);
    cudaGetSymbolAddress((void**)&wTlo, g_wTlo);
    cudaGetSymbolAddress((void**)&wfhi, g_wfhi);
    cudaGetSymbolAddress((void**)&wflo, g_wflo);
    cudaGetSymbolAddress((void**)&qthi, g_qthi);
    cudaGetSymbolAddress((void**)&qtlo, g_qtlo);
    cudaGetSymbolAddress((void**)&kthi, g_kthi);
    cudaGetSymbolAddress((void**)&ktlo, g_ktlo);

    cudaFuncSetAttribute(gemm_bf<1>, cudaFuncAttributeMaxDynamicSharedMemorySize, GEMM_SMEM);
    cudaFuncSetAttribute(gemm_bf<2>, cudaFuncAttributeMaxDynamicSharedMemorySize, GEMM_SMEM);
    cudaFuncSetAttribute(gemm_bf<3>, cudaFuncAttributeMaxDynamicSharedMemorySize, GEMM_SMEM);

    // 0) conversions: x -> bf16 hi/lo; weights -> transposed bf16 hi/lo
    cvt_x<<<(int)((size_t)MTOT * CC / (256 * 8)), 256>>>(x, xhi, xlo);
    dim3 tb(32, 8);
    tcvt<<<dim3(8, 16, 1), tb>>>(Wq, wThi, wTlo, CC, 0, 0);
    tcvt<<<dim3(8, 16, 1), tb>>>(Wk, wThi + CC * CC, wTlo + CC * CC, CC, 0, 0);
    tcvt<<<dim3(8, 16, 1), tb>>>(Wv, wThi + 2 * CC * CC, wTlo + 2 * CC * CC, CC, 0, 0);

    // 1) projections: q,k straight to transposed bf16 hi/lo; v gated + raw
    dim3 gProj(CC / 128, MTOT / 128, 1);
    gemm_bf<3><<<gProj, 128, GEMM_SMEM>>>(xhi, xlo, wThi, wTlo,
        nullptr, nullptr, qthi, qtlo, nullptr, nullptr, 0, 0);
    gemm_bf<3><<<gProj, 128, GEMM_SMEM>>>(xhi, xlo, wThi + CC * CC, wTlo + CC * CC,
        nullptr, nullptr, kthi, ktlo, nullptr, nullptr, 0, 0);
    gemm_bf<1><<<gProj, 128, GEMM_SMEM>>>(xhi, xlo, wThi + 2 * CC * CC, wTlo + 2 * CC * CC,
        nullptr, vinp, vhi, vlo, illu, nullptr, 0, 0);

    // 2) norms from transposed layout (contiguous)
    normsq_t<<<dim3(CC, BB), 256>>>(qthi, qtlo, kthi, ktlo, iq, ik);

    // 3) gram on tensor pipe + softmax
    gram_mma<<<dim3(NHEAD, BB, GSPLIT), 256>>>(kthi, ktlo, qthi, qtlo, gp);
    softmax_kernel<<<BB * NHEAD, 64>>>(gp, iq, ik, resc, attn);

    // 4) fold attention into Wp; transpose-convert to bf16 [n][k]
    weff_kernel<<<dim3(CC, BB), 256>>>(attn, Wp, weff);
    tcvt<<<dim3(8, 16, BB), tb>>>(weff, wfhi, wflo, CC,
        (size_t)CC * CC, (size_t)CC * CC);

    // 5) out_c = V @ Weff_b + bp (batched)
    gemm_bf<2><<<dim3(CC / 128, NTOK / 128, BB), 128, GEMM_SMEM>>>(
        vhi, vlo, wfhi, wflo, out, nullptr, nullptr, nullptr, nullptr, bp,
        (size_t)NTOK, (size_t)CC * CC);

    // 6) positional branch: fused dwconv -> gelu -> dwconv, added to out
    dwconv_fused<<<dim3(WW / 16, HH / 16, BB * 16), 256>>>(vinp, c1w, c2w, out);
}

// round 11
// speedup vs baseline: 1.8265x; 1.8265x over previous
#include <cuda_runtime.h>
#include <cuda_bf16.h>
#include <math.h>
#include <stdint.h>

// Problem constants
#define BB 4
#define HH 128
#define WW 128
#define CC 512
#define NTOK 16384            // H*W
#define NHEAD 8
#define DHEAD 64
#define MTOT (BB*NTOK)        // 65536
#define GSPLIT 8              // gram n-splits (CTA level); x8 warps = 64 partials
#define GS_TOT 64

typedef __nv_bfloat16 bf16;

// ---------------- scratch (device globals; no runtime allocation) ----------
static __device__ float g_vinp[(size_t)MTOT * CC];   // raw x@Wv (conv branch)
static __device__ float g_weff[(size_t)BB * CC * CC];

static __device__ __align__(16) bf16 g_xhi[(size_t)MTOT * CC];
static __device__ __align__(16) bf16 g_xlo[(size_t)MTOT * CC];
static __device__ __align__(16) bf16 g_vhi[(size_t)MTOT * CC];
static __device__ __align__(16) bf16 g_vlo[(size_t)MTOT * CC];
static __device__ __align__(16) bf16 g_wThi[3 * CC * CC];
static __device__ __align__(16) bf16 g_wTlo[3 * CC * CC];
static __device__ __align__(16) bf16 g_wfhi[(size_t)BB * CC * CC];
static __device__ __align__(16) bf16 g_wflo[(size_t)BB * CC * CC];
static __device__ __align__(16) bf16 g_qthi[(size_t)BB * CC * NTOK];  // q^T hi only
static __device__ __align__(16) bf16 g_kthi[(size_t)BB * CC * NTOK];  // k^T hi only

static __device__ float g_invq[BB * CC];
static __device__ float g_invk[BB * CC];
static __device__ float g_gpart[(size_t)GS_TOT * BB * NHEAD * DHEAD * DHEAD];
static __device__ float g_attn[(size_t)BB * NHEAD * DHEAD * DHEAD];

// =================== helpers ==============================================
__device__ __forceinline__ uint32_t s2u(const void* p) {
    uint32_t a;
    asm("{ .reg .u64 t; cvta.to.shared.u64 t, %1; cvt.u32.u64 %0, t; }"
        : "=r"(a) : "l"(p));
    return a;
}

// split 2 floats -> packed bf16 hi pair and lo pair (low half = first arg)
__device__ __forceinline__ void cvt2(float a, float b, uint32_t& h, uint32_t& l) {
    uint32_t hp;
    asm("cvt.rn.bf16x2.f32 %0, %1, %2;" : "=r"(hp) : "f"(b), "f"(a));
    float ah = __uint_as_float(hp << 16);
    float bh = __uint_as_float(hp & 0xFFFF0000u);
    float al = a - ah;
    float bl = b - bh;
    uint32_t lp;
    asm("cvt.rn.bf16x2.f32 %0, %1, %2;" : "=r"(lp) : "f"(bl), "f"(al));
    h = hp; l = lp;
}

// pack 2 floats -> bf16x2 (hi only), first arg in low half
__device__ __forceinline__ uint32_t packbf(float a, float b) {
    uint32_t hp;
    asm("cvt.rn.bf16x2.f32 %0, %1, %2;" : "=r"(hp) : "f"(b), "f"(a));
    return hp;
}

__device__ __forceinline__ void split1(float f, uint16_t& h, uint16_t& l) {
    uint32_t hp;
    asm("cvt.rn.bf16x2.f32 %0, %1, %2;" : "=r"(hp) : "f"(0.f), "f"(f));
    float hf = __uint_as_float(hp << 16);
    float lf = f - hf;
    uint32_t lp;
    asm("cvt.rn.bf16x2.f32 %0, %1, %2;" : "=r"(lp) : "f"(0.f), "f"(lf));
    h = (uint16_t)hp; l = (uint16_t)lp;
}

__device__ __forceinline__ float bfu16_to_f(uint32_t u) {
    return __uint_as_float(u << 16);
}

__device__ __forceinline__ void ldm_x4(uint32_t* r, uint32_t addr) {
    asm volatile("ldmatrix.sync.aligned.m8n8.x4.shared.b16 {%0,%1,%2,%3}, [%4];"
                 : "=r"(r[0]), "=r"(r[1]), "=r"(r[2]), "=r"(r[3]) : "r"(addr));
}
__device__ __forceinline__ void mma16816(float* c, const uint32_t* a, const uint32_t* b) {
    asm volatile(
        "mma.sync.aligned.m16n8k16.row.col.f32.bf16.bf16.f32 "
        "{%0,%1,%2,%3}, {%4,%5,%6,%7}, {%8,%9}, {%0,%1,%2,%3};"
        : "+f"(c[0]), "+f"(c[1]), "+f"(c[2]), "+f"(c[3])
        : "r"(a[0]), "r"(a[1]), "r"(a[2]), "r"(a[3]), "r"(b[0]), "r"(b[1]));
}
__device__ __forceinline__ void cp16(uint32_t dst, const void* src) {
    asm volatile("cp.async.cg.shared.global [%0], [%1], 16;" :: "r"(dst), "l"(src));
}

// =================== conversion kernels ====================================
__global__ void cvt_x(const float* __restrict__ x, bf16* __restrict__ xhi,
                      bf16* __restrict__ xlo)
{
    size_t g = ((size_t)blockIdx.x * 256 + threadIdx.x);
    const float4* p = (const float4*)(x + g * 8);
    float4 a = p[0], b = p[1];
    uint4 h, l;
    cvt2(a.x, a.y, h.x, l.x); cvt2(a.z, a.w, h.y, l.y);
    cvt2(b.x, b.y, h.z, l.z); cvt2(b.z, b.w, h.w, l.w);
    ((uint4*)xhi)[g] = h;
    ((uint4*)xlo)[g] = l;
}

// transpose + convert: src fp32 [R][512] (batched) -> dst bf16 [512][R] hi/lo
__global__ void tcvt(const float* __restrict__ src, bf16* __restrict__ dhi,
                     bf16* __restrict__ dlo, int R, size_t sStride, size_t dStride)
{
    __shared__ uint16_t shh[32][65];
    __shared__ uint16_t shl[32][65];
    int z = blockIdx.z;
    const float* s = src + (size_t)z * sStride;
    int c = blockIdx.y * 32 + threadIdx.x;
    int nb = blockIdx.x * 64;
#pragma unroll
    for (int i = 0; i < 8; i++) {
        int n = threadIdx.y + i * 8;
        float f = s[(size_t)(nb + n) * CC + c];
        uint16_t h, l;
        split1(f, h, l);
        shh[threadIdx.x][n] = h;
        shl[threadIdx.x][n] = l;
    }
    __syncthreads();
#pragma unroll
    for (int i = 0; i < 4; i++) {
        int cl = threadIdx.y + i * 8;
        int row = blockIdx.y * 32 + cl;
        size_t u32idx = ((size_t)row * R + nb) >> 1;
        uint32_t h = (uint32_t)shh[cl][threadIdx.x * 2] |
                     ((uint32_t)shh[cl][threadIdx.x * 2 + 1] << 16);
        uint32_t l = (uint32_t)shl[cl][threadIdx.x * 2] |
                     ((uint32_t)shl[cl][threadIdx.x * 2 + 1] << 16);
        ((uint32_t*)(dhi + (size_t)z * dStride))[u32idx + threadIdx.x] = h;
        ((uint32_t*)(dlo + (size_t)z * dStride))[u32idx + threadIdx.x] = l;
    }
}

// =================== pipelined bf16 GEMM (3-term, round-6 config) ==========
// C[M,512] = A[M,512] @ Bt[512,512]^T, operands bf16 hi/lo (3-term split).
// CTA 128x128, 8 warps (64x32), k-chunk 32, 2-stage cp.async, 2 CTAs/SM.
// MODE 1: C2 = raw fp32; Vhi/Vlo = bf16 split of raw*illu
// MODE 2: C = A@B + bias
#define KCH 32
#define ROWB 80
#define MATB (128 * ROWB)        // 10240
#define STAGEB (4 * MATB)        // 40960
#define GEMM_SMEM (2 * STAGEB)   // 81920

__device__ __forceinline__ void stage_issue(
    uint32_t sb, int tid,
    const bf16* aHi, const bf16* aLo, const bf16* bHi, const bf16* bLo)
{
    const bf16* g[4] = {aHi, aLo, bHi, bLo};
#pragma unroll
    for (int m = 0; m < 4; m++) {
#pragma unroll
        for (int it = 0; it < 2; it++) {
            int u = tid + it * 256;
            int r = u >> 2, seg = u & 3;
            cp16(sb + m * MATB + r * ROWB + seg * 16,
                 g[m] + (size_t)r * CC + seg * 8);
        }
    }
    asm volatile("cp.async.commit_group;" ::: "memory");
}

template <int MODE>
__global__ void __launch_bounds__(256, 2) gemm_bf(
    const bf16* __restrict__ Ahi, const bf16* __restrict__ Alo,
    const bf16* __restrict__ Bhi, const bf16* __restrict__ Blo,
    float* __restrict__ C, float* __restrict__ C2,
    bf16* __restrict__ Vhi, bf16* __restrict__ Vlo,
    const float* __restrict__ illu, const float* __restrict__ bias,
    size_t zRow, size_t sB)
{
    extern __shared__ char smem[];
    const uint32_t sb0 = s2u(smem);
    const int tid = threadIdx.x;
    const int wid = tid >> 5, lane = tid & 31;
    const int wm = wid & 1, wn = wid >> 1;

    const size_t row0 = (size_t)blockIdx.y * 128 + (size_t)blockIdx.z * zRow;
    const int n0 = blockIdx.x * 128;
    const size_t boff = (size_t)blockIdx.z * sB + (size_t)n0 * CC;

    float acc[4][4][4];
#pragma unroll
    for (int i = 0; i < 4; i++)
#pragma unroll
        for (int j = 0; j < 4; j++)
#pragma unroll
            for (int t = 0; t < 4; t++) acc[i][j][t] = 0.f;

    const int a_row = wm * 64 + (lane & 15);
    const int a_koff = (lane >> 4) * 16;
    const int b_row4 = wn * 32 + ((lane >> 4) & 1) * 8 + (lane & 7);
    const int b_koff4 = ((lane >> 3) & 1) * 16;

    stage_issue(sb0, tid, Ahi + row0 * CC, Alo + row0 * CC, Bhi + boff, Blo + boff);
    stage_issue(sb0 + STAGEB, tid, Ahi + row0 * CC + KCH, Alo + row0 * CC + KCH,
                Bhi + boff + KCH, Blo + boff + KCH);

    for (int ch = 0; ch < 16; ch++) {
        const int cur = ch & 1;
        if (ch < 15) asm volatile("cp.async.wait_group 1;" ::: "memory");
        else         asm volatile("cp.async.wait_group 0;" ::: "memory");
        __syncthreads();

        const uint32_t base = sb0 + cur * STAGEB;
        const uint32_t aHs = base, aLs = base + MATB;
        const uint32_t bHs = base + 2 * MATB, bLs = base + 3 * MATB;
#pragma unroll
        for (int ks = 0; ks < 2; ks++) {
            const int kb = ks * 32;
            uint32_t ah[4][4], al[4][4], bh[4][2], bl[4][2];
#pragma unroll
            for (int i = 0; i < 4; i++) {
                uint32_t ra = (a_row + i * 16) * ROWB + kb + a_koff;
                ldm_x4(ah[i], aHs + ra);
                ldm_x4(al[i], aLs + ra);
            }
#pragma unroll
            for (int jp = 0; jp < 2; jp++) {
                uint32_t rb = (b_row4 + jp * 16) * ROWB + kb + b_koff4;
                uint32_t t4[4];
                ldm_x4(t4, bHs + rb);
                bh[jp * 2][0] = t4[0]; bh[jp * 2][1] = t4[1];
                bh[jp * 2 + 1][0] = t4[2]; bh[jp * 2 + 1][1] = t4[3];
                ldm_x4(t4, bLs + rb);
                bl[jp * 2][0] = t4[0]; bl[jp * 2][1] = t4[1];
                bl[jp * 2 + 1][0] = t4[2]; bl[jp * 2 + 1][1] = t4[3];
            }
#pragma unroll
            for (int i = 0; i < 4; i++)
#pragma unroll
                for (int j = 0; j < 4; j++) {
                    mma16816(acc[i][j], ah[i], bh[j]);
                    mma16816(acc[i][j], ah[i], bl[j]);
                    mma16816(acc[i][j], al[i], bh[j]);
                }
        }
        __syncthreads();
        if (ch + 2 < 16) {
            const int k0 = (ch + 2) * KCH;
            stage_issue(base, tid, Ahi + row0 * CC + k0, Alo + row0 * CC + k0,
                        Bhi + boff + k0, Blo + boff + k0);
        }
    }

    // ---- epilogue ----
    const int mrow = wm * 64 + (lane >> 2);
    const int mcol = wn * 32 + (lane & 3) * 2;

#pragma unroll
    for (int i = 0; i < 4; i++) {
#pragma unroll
        for (int half = 0; half < 2; half++) {
            size_t r = row0 + mrow + i * 16 + half * 8;
            size_t base = r * CC + n0 + mcol;
#pragma unroll
            for (int j = 0; j < 4; j++) {
                float2 v2;
                v2.x = acc[i][j][half * 2 + 0];
                v2.y = acc[i][j][half * 2 + 1];
                size_t off = base + j * 8;
                if (MODE == 1) {
                    float2 iv = *(const float2*)(illu + off);
                    *(float2*)(C2 + off) = v2;
                    uint32_t h, l;
                    cvt2(v2.x * iv.x, v2.y * iv.y, h, l);
                    ((uint32_t*)Vhi)[off >> 1] = h;
                    ((uint32_t*)Vlo)[off >> 1] = l;
                } else {
                    float2 bv = *(const float2*)(bias + n0 + mcol + j * 8);
                    v2.x += bv.x; v2.y += bv.y;
                    *(float2*)(C + off) = v2;
                }
            }
        }
    }
}

// =================== 1-term bf16 GEMM for Q/K (hi-only) ====================
// O^T[b][col][row] = bf16( A_hi[M,512] @ B_hi[512,512]^T ), hi only output.
// Same tile config as gemm_bf, but single hi operand per side -> 1 MMA/term.
#define STAGE1B (2 * MATB)         // 20480
#define GEMM1_SMEM (2 * STAGE1B)   // 40960

__device__ __forceinline__ void stage_issue1(
    uint32_t sb, int tid, const bf16* aHi, const bf16* bHi)
{
    const bf16* g[2] = {aHi, bHi};
#pragma unroll
    for (int m = 0; m < 2; m++) {
#pragma unroll
        for (int it = 0; it < 2; it++) {
            int u = tid + it * 256;
            int r = u >> 2, seg = u & 3;
            cp16(sb + m * MATB + r * ROWB + seg * 16,
                 g[m] + (size_t)r * CC + seg * 8);
        }
    }
    asm volatile("cp.async.commit_group;" ::: "memory");
}

__global__ void __launch_bounds__(256, 2) gemm_1t(
    const bf16* __restrict__ Ahi, const bf16* __restrict__ Bhi,
    bf16* __restrict__ Ohi)
{
    extern __shared__ char smem[];
    const uint32_t sb0 = s2u(smem);
    const int tid = threadIdx.x;
    const int wid = tid >> 5, lane = tid & 31;
    const int wm = wid & 1, wn = wid >> 1;

    const size_t row0 = (size_t)blockIdx.y * 128;
    const int n0 = blockIdx.x * 128;
    const size_t boff = (size_t)n0 * CC;

    float acc[4][4][4];
#pragma unroll
    for (int i = 0; i < 4; i++)
#pragma unroll
        for (int j = 0; j < 4; j++)
#pragma unroll
            for (int t = 0; t < 4; t++) acc[i][j][t] = 0.f;

    const int a_row = wm * 64 + (lane & 15);
    const int a_koff = (lane >> 4) * 16;
    const int b_row4 = wn * 32 + ((lane >> 4) & 1) * 8 + (lane & 7);
    const int b_koff4 = ((lane >> 3) & 1) * 16;

    stage_issue1(sb0, tid, Ahi + row0 * CC, Bhi + boff);
    stage_issue1(sb0 + STAGE1B, tid, Ahi + row0 * CC + KCH, Bhi + boff + KCH);

    for (int ch = 0; ch < 16; ch++) {
        const int cur = ch & 1;
        if (ch < 15) asm volatile("cp.async.wait_group 1;" ::: "memory");
        else         asm volatile("cp.async.wait_group 0;" ::: "memory");
        __syncthreads();

        const uint32_t base = sb0 + cur * STAGE1B;
        const uint32_t aHs = base, bHs = base + MATB;
#pragma unroll
        for (int ks = 0; ks < 2; ks++) {
            const int kb = ks * 32;
            uint32_t ah[4][4], bh[4][2];
#pragma unroll
            for (int i = 0; i < 4; i++) {
                uint32_t ra = (a_row + i * 16) * ROWB + kb + a_koff;
                ldm_x4(ah[i], aHs + ra);
            }
#pragma unroll
            for (int jp = 0; jp < 2; jp++) {
                uint32_t rb = (b_row4 + jp * 16) * ROWB + kb + b_koff4;
                uint32_t t4[4];
                ldm_x4(t4, bHs + rb);
                bh[jp * 2][0] = t4[0]; bh[jp * 2][1] = t4[1];
                bh[jp * 2 + 1][0] = t4[2]; bh[jp * 2 + 1][1] = t4[3];
            }
#pragma unroll
            for (int i = 0; i < 4; i++)
#pragma unroll
                for (int j = 0; j < 4; j++)
                    mma16816(acc[i][j], ah[i], bh[j]);
        }
        __syncthreads();
        if (ch + 2 < 16) {
            const int k0 = (ch + 2) * KCH;
            stage_issue1(base, tid, Ahi + row0 * CC + k0, Bhi + boff + k0);
        }
    }

    // ---- epilogue: transposed bf16 hi output via smem transpose ----
    const int mrow = wm * 64 + (lane >> 2);
    const int mcol = wn * 32 + (lane & 3) * 2;

    uint16_t* shh = (uint16_t*)smem;              // [128 cols][130]
    __syncthreads();
#pragma unroll
    for (int i = 0; i < 4; i++)
#pragma unroll
        for (int half = 0; half < 2; half++) {
            int row = mrow + i * 16 + half * 8;
#pragma unroll
            for (int j = 0; j < 4; j++) {
                int col = mcol + j * 8;
                uint32_t h = packbf(acc[i][j][half * 2 + 0], acc[i][j][half * 2 + 1]);
                shh[col * 130 + row] = (uint16_t)h;
                shh[(col + 1) * 130 + row] = (uint16_t)(h >> 16);
            }
        }
    __syncthreads();
    const int b = (int)(blockIdx.y >> 7);
    const size_t nl0 = (size_t)(blockIdx.y & 127) * 128;
    uint32_t* dh = (uint32_t*)Ohi;
#pragma unroll
    for (int it = 0; it < 32; it++) {
        int c = it * 4 + (tid >> 6);
        int w = tid & 63;
        uint32_t hv = *(uint32_t*)(&shh[c * 130 + 2 * w]);
        size_t idx = ((((size_t)b * CC + n0 + c) * NTOK + nl0) >> 1) + w;
        dh[idx] = hv;
    }
}

// ------------- norms from transposed bf16 hi (contiguous rows) -------------
__global__ void normsq_t(const bf16* __restrict__ qh_, const bf16* __restrict__ kh_,
                         float* __restrict__ iq, float* __restrict__ ik)
{
    const int c = blockIdx.x, b = blockIdx.y;
    const int tid = threadIdx.x;
    const size_t b32 = (((size_t)b * CC + c) * NTOK) >> 1;
    const uint32_t* qh = (const uint32_t*)qh_ + b32;
    const uint32_t* kh = (const uint32_t*)kh_ + b32;

    float sq = 0.f, sk = 0.f;
    for (int i = tid; i < NTOK / 2; i += 256) {
        uint32_t h = qh[i];
        float f0 = bfu16_to_f(h & 0xFFFF);
        float f1 = bfu16_to_f(h >> 16);
        sq += f0 * f0 + f1 * f1;
        h = kh[i];
        f0 = bfu16_to_f(h & 0xFFFF);
        f1 = bfu16_to_f(h >> 16);
        sk += f0 * f0 + f1 * f1;
    }
    __shared__ float red[2][256];
    red[0][tid] = sq; red[1][tid] = sk;
    __syncthreads();
    for (int s = 128; s > 0; s >>= 1) {
        if (tid < s) {
            red[0][tid] += red[0][tid + s];
            red[1][tid] += red[1][tid + s];
        }
        __syncthreads();
    }
    if (tid == 0) {
        iq[b * CC + c] = 1.f / fmaxf(sqrtf(red[0][0]), 1e-12f);
        ik[b * CC + c] = 1.f / fmaxf(sqrtf(red[1][0]), 1e-12f);
    }
}

// ------------- Gram via mma with direct-LDG fragments (1-term hi) ----------
__global__ void __launch_bounds__(256) gram_mma(
    const bf16* __restrict__ KThi, const bf16* __restrict__ QThi,
    float* __restrict__ part)
{
    const int h = blockIdx.x, b = blockIdx.y, s = blockIdx.z;
    const int wid = threadIdx.x >> 5, lane = threadIdx.x & 31;
    const int nbase = s * (NTOK / GSPLIT) + wid * 256;

    const size_t rowbase = ((size_t)b * CC + h * DHEAD) * NTOK;
    const bf16* Kh = KThi + rowbase;
    const bf16* Qh = QThi + rowbase;

    float acc[4][8][4];
#pragma unroll
    for (int i = 0; i < 4; i++)
#pragma unroll
        for (int j = 0; j < 8; j++)
#pragma unroll
            for (int t = 0; t < 4; t++) acc[i][j][t] = 0.f;

    const int rsel = lane >> 2;
    const int csel = (lane & 3) * 2;

    for (int step = 0; step < 16; step++) {
        const int nb = nbase + step * 16 + csel;
        uint32_t ah[4][4];
#pragma unroll
        for (int mt = 0; mt < 4; mt++) {
            const size_t r0 = (size_t)(mt * 16 + rsel) * NTOK;
            const size_t r8 = r0 + 8 * NTOK;
            ah[mt][0] = *(const uint32_t*)(Kh + r0 + nb);
            ah[mt][1] = *(const uint32_t*)(Kh + r8 + nb);
            ah[mt][2] = *(const uint32_t*)(Kh + r0 + nb + 8);
            ah[mt][3] = *(const uint32_t*)(Kh + r8 + nb + 8);
        }
#pragma unroll
        for (int nt = 0; nt < 8; nt++) {
            const size_t q0 = (size_t)(nt * 8 + rsel) * NTOK;
            uint32_t bh[2];
            bh[0] = *(const uint32_t*)(Qh + q0 + nb);
            bh[1] = *(const uint32_t*)(Qh + q0 + nb + 8);
#pragma unroll
            for (int mt = 0; mt < 4; mt++)
                mma16816(acc[mt][nt], ah[mt], bh);
        }
    }

    const int sp = s * 8 + wid;
    float* dst = part + (((size_t)sp * BB + b) * NHEAD + h) * 4096;
#pragma unroll
    for (int mt = 0; mt < 4; mt++)
#pragma unroll
        for (int nt = 0; nt < 8; nt++) {
            int r = mt * 16 + rsel, c = nt * 8 + csel;
            dst[r * 64 + c]           = acc[mt][nt][0];
            dst[r * 64 + c + 1]       = acc[mt][nt][1];
            dst[(r + 8) * 64 + c]     = acc[mt][nt][2];
            dst[(r + 8) * 64 + c + 1] = acc[mt][nt][3];
        }
}

// ------------- softmax over e ----------------------------------------------
__global__ void softmax_kernel(const float* __restrict__ part,
                               const float* __restrict__ iq,
                               const float* __restrict__ ik,
                               const float* __restrict__ rescale,
                               float* __restrict__ attn)
{
    int bh = blockIdx.x;
    int b = bh / NHEAD, h = bh % NHEAD;
    int d = threadIdx.x;

    __shared__ float iq_s[64];
    iq_s[d] = iq[b * CC + h * DHEAD + d];
    float ik_d = ik[b * CC + h * DHEAD + d];
    float resc = rescale[h];
    __syncthreads();

    float row[64];
#pragma unroll
    for (int e = 0; e < 64; e++) row[e] = 0.f;
    for (int sp = 0; sp < GS_TOT; sp++) {
        const float* p = part + (((size_t)sp * BB + b) * NHEAD + h) * 4096 + d * 64;
#pragma unroll 8
        for (int e = 0; e < 64; e++) row[e] += p[e];
    }
    float m = -1e30f;
#pragma unroll
    for (int e = 0; e < 64; e++) {
        row[e] = row[e] * ik_d * iq_s[e] * resc;
        m = fmaxf(m, row[e]);
    }
    float sum = 0.f;
#pragma unroll
    for (int e = 0; e < 64; e++) {
        row[e] = __expf(row[e] - m);
        sum += row[e];
    }
    float inv = 1.f / sum;
    float* dst = attn + ((size_t)(b * NHEAD + h)) * 4096 + d * 64;
#pragma unroll
    for (int e = 0; e < 64; e++) dst[e] = row[e] * inv;
}

// ------------- Weff[b][h*64+e][j] = sum_d attn[b,h,d,e] * Wp[h*64+d][j] -----
__global__ void weff_kernel(const float* __restrict__ attn,
                            const float* __restrict__ Wp,
                            float* __restrict__ weff)
{
    int eg = blockIdx.x;
    int b = blockIdx.y;
    int tid = threadIdx.x;
    int h = eg >> 6, e = eg & 63;

    __shared__ float a_s[64];
    if (tid < 64) a_s[tid] = attn[((size_t)(b * NHEAD + h) * 64 + tid) * 64 + e];
    __syncthreads();

    for (int j = tid; j < CC; j += 256) {
        float acc = 0.f;
#pragma unroll
        for (int d = 0; d < 64; d++)
            acc += a_s[d] * Wp[(size_t)(h * 64 + d) * CC + j];
        weff[((size_t)b * CC + eg) * CC + j] = acc;
    }
}

// ------------- fused dwconv3 -> GELU -> dwconv3 (NHWC), SAME padding -------
__global__ void __launch_bounds__(256) dwconv_fused(
    const float* __restrict__ in, const float* __restrict__ w1,
    const float* __restrict__ w2, float* __restrict__ out)
{
    __shared__ float t[18 * 18 * 32];
    const int chb = (blockIdx.z & 15) * 32;
    const int b = blockIdx.z >> 4;
    const int x0 = blockIdx.x * 16, y0 = blockIdx.y * 16;
    const int ch = threadIdx.x & 31;
    const int sp = threadIdx.x >> 5;

    float wv[9];
#pragma unroll
    for (int k = 0; k < 9; k++) wv[k] = w1[(chb + ch) * 9 + k];

    for (int p = sp; p < 324; p += 8) {
        int ly = p / 18, lx = p - ly * 18;
        int gy = y0 + ly - 1, gx = x0 + lx - 1;
        float val = 0.f;
        if (gy >= 0 && gy < HH && gx >= 0 && gx < WW) {
            float acc = 0.f;
#pragma unroll
            for (int dy = -1; dy <= 1; dy++) {
                int yy = gy + dy;
                if (yy < 0 || yy > HH - 1) continue;
#pragma unroll
                for (int dx = -1; dx <= 1; dx++) {
                    int xx = gx + dx;
                    if (xx < 0 || xx > WW - 1) continue;
                    acc += in[(((size_t)b * HH + yy) * WW + xx) * CC + chb + ch] *
                           wv[(dy + 1) * 3 + (dx + 1)];
                }
            }
            val = 0.5f * acc * (1.f + erff(acc * 0.70710678118654752f));
        }
        t[p * 32 + ch] = val;
    }
    __syncthreads();

#pragma unroll
    for (int k = 0; k < 9; k++) wv[k] = w2[(chb + ch) * 9 + k];

    for (int p = sp; p < 256; p += 8) {
        int ly = p >> 4, lx = p & 15;
        float acc = 0.f;
#pragma unroll
        for (int dy = 0; dy < 3; dy++)
#pragma unroll
            for (int dx = 0; dx < 3; dx++)
                acc += t[((ly + dy) * 18 + lx + dx) * 32 + ch] * wv[dy * 3 + dx];
        size_t o = (((size_t)b * HH + y0 + ly) * WW + x0 + lx) * CC + chb + ch;
        out[o] += acc;
    }
}

// ---------------------------------------------------------------------------
extern "C" void kernel_launch(void* const* d_in, const int* in_sizes, int n_in,
                              void* d_out, int out_size)
{
    const float* x    = (const float*)d_in[0];
    const float* illu = (const float*)d_in[1];
    const float* Wq   = (const float*)d_in[2];
    const float* Wk   = (const float*)d_in[3];
    const float* Wv   = (const float*)d_in[4];
    const float* resc = (const float*)d_in[5];
    const float* Wp   = (const float*)d_in[6];
    const float* bp   = (const float*)d_in[7];
    const float* c1w  = (const float*)d_in[8];
    const float* c2w  = (const float*)d_in[9];
    float* out = (float*)d_out;

    float *vinp, *weff, *iq, *ik, *gp, *attn;
    bf16 *xhi, *xlo, *vhi, *vlo, *wThi, *wTlo, *wfhi, *wflo;
    bf16 *qthi, *kthi;
    cudaGetSymbolAddress((void**)&vinp, g_vinp);
    cudaGetSymbolAddress((void**)&weff, g_weff);
    cudaGetSymbolAddress((void**)&iq, g_invq);
    cudaGetSymbolAddress((void**)&ik, g_invk);
    cudaGetSymbolAddress((void**)&gp, g_gpart);
    cudaGetSymbolAddress((void**)&attn, g_attn);
    cudaGetSymbolAddress((void**)&xhi, g_xhi);
    cudaGetSymbolAddress((void**)&xlo, g_xlo);
    cudaGetSymbolAddress((void**)&vhi, g_vhi);
    cudaGetSymbolAddress((void**)&vlo, g_vlo);
    cudaGetSymbolAddress((void**)&wThi, g_wThi);
    cudaGetSymbolAddress((void**)&wTlo, g_wTlo);
    cudaGetSymbolAddress((void**)&wfhi, g_wfhi);
    cudaGetSymbolAddress((void**)&wflo, g_wflo);
    cudaGetSymbolAddress((void**)&qthi, g_qthi);
    cudaGetSymbolAddress((void**)&kthi, g_kthi);

    cudaFuncSetAttribute(gemm_bf<1>, cudaFuncAttributeMaxDynamicSharedMemorySize, GEMM_SMEM);
    cudaFuncSetAttribute(gemm_bf<2>, cudaFuncAttributeMaxDynamicSharedMemorySize, GEMM_SMEM);
    cudaFuncSetAttribute(gemm_1t, cudaFuncAttributeMaxDynamicSharedMemorySize, GEMM1_SMEM);

    // 0) conversions: x -> bf16 hi/lo; weights -> transposed bf16 hi/lo
    cvt_x<<<(int)((size_t)MTOT * CC / (256 * 8)), 256>>>(x, xhi, xlo);
    dim3 tb(32, 8);
    tcvt<<<dim3(8, 16, 1), tb>>>(Wq, wThi, wTlo, CC, 0, 0);
    tcvt<<<dim3(8, 16, 1), tb>>>(Wk, wThi + CC * CC, wTlo + CC * CC, CC, 0, 0);
    tcvt<<<dim3(8, 16, 1), tb>>>(Wv, wThi + 2 * CC * CC, wTlo + 2 * CC * CC, CC, 0, 0);

    // 1) projections: q,k 1-term hi-only -> transposed; v 3-term gated + raw
    dim3 gProj(CC / 128, MTOT / 128, 1);
    gemm_1t<<<gProj, 256, GEMM1_SMEM>>>(xhi, wThi, qthi);
    gemm_1t<<<gProj, 256, GEMM1_SMEM>>>(xhi, wThi + CC * CC, kthi);
    gemm_bf<1><<<gProj, 256, GEMM_SMEM>>>(xhi, xlo, wThi + 2 * CC * CC, wTlo + 2 * CC * CC,
        nullptr, vinp, vhi, vlo, illu, nullptr, 0, 0);

    // 2) norms from transposed hi layout (consistent with gram operands)
    normsq_t<<<dim3(CC, BB), 256>>>(qthi, kthi, iq, ik);

    // 3) gram on tensor pipe (1-term) + softmax
    gram_mma<<<dim3(NHEAD, BB, GSPLIT), 256>>>(kthi, qthi, gp);
    softmax_kernel<<<BB * NHEAD, 64>>>(gp, iq, ik, resc, attn);

    // 4) fold attention into Wp; transpose-convert to bf16 [n][k]
    weff_kernel<<<dim3(CC, BB), 256>>>(attn, Wp, weff);
    tcvt<<<dim3(8, 16, BB), tb>>>(weff, wfhi, wflo, CC,
        (size_t)CC * CC, (size_t)CC * CC);

    // 5) out_c = V @ Weff_b + bp (batched, 3-term)
    gemm_bf<2><<<dim3(CC / 128, NTOK / 128, BB), 256, GEMM_SMEM>>>(
        vhi, vlo, wfhi, wflo, out, nullptr, nullptr, nullptr, nullptr, bp,
        (size_t)NTOK, (size_t)CC * CC);

    // 6) positional branch: fused dwconv -> gelu -> dwconv, added to out
    dwconv_fused<<<dim3(WW / 16, HH / 16, BB * 16), 256>>>(vinp, c1w, c2w, out);
}

// round 12
// speedup vs baseline: 1.9119x; 1.0467x over previous
#include <cuda_runtime.h>
#include <cuda_bf16.h>
#include <math.h>
#include <stdint.h>

// Problem constants
#define BB 4
#define HH 128
#define WW 128
#define CC 512
#define NTOK 16384            // H*W
#define NHEAD 8
#define DHEAD 64
#define MTOT (BB*NTOK)        // 65536
#define GSPLIT 8              // gram n-splits (CTA level); x8 warps = 64 partials
#define GS_TOT 64

typedef __nv_bfloat16 bf16;

// ---------------- scratch (device globals; no runtime allocation) ----------
static __device__ float g_vinp[(size_t)MTOT * CC];   // raw x@Wv (conv branch)
static __device__ float g_weff[(size_t)BB * CC * CC];

static __device__ __align__(16) bf16 g_xhi[(size_t)MTOT * CC];
static __device__ __align__(16) bf16 g_xlo[(size_t)MTOT * CC];
static __device__ __align__(16) bf16 g_vhi[(size_t)MTOT * CC];
static __device__ __align__(16) bf16 g_vlo[(size_t)MTOT * CC];
static __device__ __align__(16) bf16 g_wThi[3 * CC * CC];
static __device__ __align__(16) bf16 g_wTlo[3 * CC * CC];
static __device__ __align__(16) bf16 g_wfhi[(size_t)BB * CC * CC];
static __device__ __align__(16) bf16 g_wflo[(size_t)BB * CC * CC];
static __device__ __align__(16) bf16 g_qthi[(size_t)BB * CC * NTOK];  // q^T hi only
static __device__ __align__(16) bf16 g_kthi[(size_t)BB * CC * NTOK];  // k^T hi only

static __device__ float g_nq[(size_t)BB * 128 * CC];   // q colsumsq partials
static __device__ float g_nk[(size_t)BB * 128 * CC];   // k colsumsq partials
static __device__ float g_invq[BB * CC];
static __device__ float g_invk[BB * CC];
static __device__ float g_gpart[(size_t)GS_TOT * BB * NHEAD * DHEAD * DHEAD];
static __device__ float g_attn[(size_t)BB * NHEAD * DHEAD * DHEAD];

// =================== helpers ==============================================
__device__ __forceinline__ uint32_t s2u(const void* p) {
    uint32_t a;
    asm("{ .reg .u64 t; cvta.to.shared.u64 t, %1; cvt.u32.u64 %0, t; }"
        : "=r"(a) : "l"(p));
    return a;
}

// split 2 floats -> packed bf16 hi pair and lo pair (low half = first arg)
__device__ __forceinline__ void cvt2(float a, float b, uint32_t& h, uint32_t& l) {
    uint32_t hp;
    asm("cvt.rn.bf16x2.f32 %0, %1, %2;" : "=r"(hp) : "f"(b), "f"(a));
    float ah = __uint_as_float(hp << 16);
    float bh = __uint_as_float(hp & 0xFFFF0000u);
    float al = a - ah;
    float bl = b - bh;
    uint32_t lp;
    asm("cvt.rn.bf16x2.f32 %0, %1, %2;" : "=r"(lp) : "f"(bl), "f"(al));
    h = hp; l = lp;
}

// pack 2 floats -> bf16x2 (hi only), first arg in low half
__device__ __forceinline__ uint32_t packbf(float a, float b) {
    uint32_t hp;
    asm("cvt.rn.bf16x2.f32 %0, %1, %2;" : "=r"(hp) : "f"(b), "f"(a));
    return hp;
}

__device__ __forceinline__ void split1(float f, uint16_t& h, uint16_t& l) {
    uint32_t hp;
    asm("cvt.rn.bf16x2.f32 %0, %1, %2;" : "=r"(hp) : "f"(0.f), "f"(f));
    float hf = __uint_as_float(hp << 16);
    float lf = f - hf;
    uint32_t lp;
    asm("cvt.rn.bf16x2.f32 %0, %1, %2;" : "=r"(lp) : "f"(0.f), "f"(lf));
    h = (uint16_t)hp; l = (uint16_t)lp;
}

__device__ __forceinline__ void ldm_x4(uint32_t* r, uint32_t addr) {
    asm volatile("ldmatrix.sync.aligned.m8n8.x4.shared.b16 {%0,%1,%2,%3}, [%4];"
                 : "=r"(r[0]), "=r"(r[1]), "=r"(r[2]), "=r"(r[3]) : "r"(addr));
}
__device__ __forceinline__ void mma16816(float* c, const uint32_t* a, const uint32_t* b) {
    asm volatile(
        "mma.sync.aligned.m16n8k16.row.col.f32.bf16.bf16.f32 "
        "{%0,%1,%2,%3}, {%4,%5,%6,%7}, {%8,%9}, {%0,%1,%2,%3};"
        : "+f"(c[0]), "+f"(c[1]), "+f"(c[2]), "+f"(c[3])
        : "r"(a[0]), "r"(a[1]), "r"(a[2]), "r"(a[3]), "r"(b[0]), "r"(b[1]));
}
__device__ __forceinline__ void cp16(uint32_t dst, const void* src) {
    asm volatile("cp.async.cg.shared.global [%0], [%1], 16;" :: "r"(dst), "l"(src));
}

// =================== conversion kernels ====================================
__global__ void cvt_x(const float* __restrict__ x, bf16* __restrict__ xhi,
                      bf16* __restrict__ xlo)
{
    size_t g = ((size_t)blockIdx.x * 256 + threadIdx.x);
    const float4* p = (const float4*)(x + g * 8);
    float4 a = p[0], b = p[1];
    uint4 h, l;
    cvt2(a.x, a.y, h.x, l.x); cvt2(a.z, a.w, h.y, l.y);
    cvt2(b.x, b.y, h.z, l.z); cvt2(b.z, b.w, h.w, l.w);
    ((uint4*)xhi)[g] = h;
    ((uint4*)xlo)[g] = l;
}

// transpose + convert: src fp32 [R][512] (batched) -> dst bf16 [512][R] hi/lo
__global__ void tcvt(const float* __restrict__ src, bf16* __restrict__ dhi,
                     bf16* __restrict__ dlo, int R, size_t sStride, size_t dStride)
{
    __shared__ uint16_t shh[32][65];
    __shared__ uint16_t shl[32][65];
    int z = blockIdx.z;
    const float* s = src + (size_t)z * sStride;
    int c = blockIdx.y * 32 + threadIdx.x;
    int nb = blockIdx.x * 64;
#pragma unroll
    for (int i = 0; i < 8; i++) {
        int n = threadIdx.y + i * 8;
        float f = s[(size_t)(nb + n) * CC + c];
        uint16_t h, l;
        split1(f, h, l);
        shh[threadIdx.x][n] = h;
        shl[threadIdx.x][n] = l;
    }
    __syncthreads();
#pragma unroll
    for (int i = 0; i < 4; i++) {
        int cl = threadIdx.y + i * 8;
        int row = blockIdx.y * 32 + cl;
        size_t u32idx = ((size_t)row * R + nb) >> 1;
        uint32_t h = (uint32_t)shh[cl][threadIdx.x * 2] |
                     ((uint32_t)shh[cl][threadIdx.x * 2 + 1] << 16);
        uint32_t l = (uint32_t)shl[cl][threadIdx.x * 2] |
                     ((uint32_t)shl[cl][threadIdx.x * 2 + 1] << 16);
        ((uint32_t*)(dhi + (size_t)z * dStride))[u32idx + threadIdx.x] = h;
        ((uint32_t*)(dlo + (size_t)z * dStride))[u32idx + threadIdx.x] = l;
    }
}

// =================== pipelined bf16 GEMM (3-term, round-6 config) ==========
// C[M,512] = A[M,512] @ Bt[512,512]^T, operands bf16 hi/lo (3-term split).
// CTA 128x128, 8 warps (64x32), k-chunk 32, 2-stage cp.async, 2 CTAs/SM.
// MODE 1: C2 = raw fp32; Vhi/Vlo = bf16 split of raw*illu
// MODE 2: C = A@B + bias
#define KCH 32
#define ROWB 80
#define MATB (128 * ROWB)        // 10240
#define STAGEB (4 * MATB)        // 40960
#define GEMM_SMEM (2 * STAGEB)   // 81920

__device__ __forceinline__ void stage_issue(
    uint32_t sb, int tid,
    const bf16* aHi, const bf16* aLo, const bf16* bHi, const bf16* bLo)
{
    const bf16* g[4] = {aHi, aLo, bHi, bLo};
#pragma unroll
    for (int m = 0; m < 4; m++) {
#pragma unroll
        for (int it = 0; it < 2; it++) {
            int u = tid + it * 256;
            int r = u >> 2, seg = u & 3;
            cp16(sb + m * MATB + r * ROWB + seg * 16,
                 g[m] + (size_t)r * CC + seg * 8);
        }
    }
    asm volatile("cp.async.commit_group;" ::: "memory");
}

template <int MODE>
__global__ void __launch_bounds__(256, 2) gemm_bf(
    const bf16* __restrict__ Ahi, const bf16* __restrict__ Alo,
    const bf16* __restrict__ Bhi, const bf16* __restrict__ Blo,
    float* __restrict__ C, float* __restrict__ C2,
    bf16* __restrict__ Vhi, bf16* __restrict__ Vlo,
    const float* __restrict__ illu, const float* __restrict__ bias,
    size_t zRow, size_t sB)
{
    extern __shared__ char smem[];
    const uint32_t sb0 = s2u(smem);
    const int tid = threadIdx.x;
    const int wid = tid >> 5, lane = tid & 31;
    const int wm = wid & 1, wn = wid >> 1;

    const size_t row0 = (size_t)blockIdx.y * 128 + (size_t)blockIdx.z * zRow;
    const int n0 = blockIdx.x * 128;
    const size_t boff = (size_t)blockIdx.z * sB + (size_t)n0 * CC;

    float acc[4][4][4];
#pragma unroll
    for (int i = 0; i < 4; i++)
#pragma unroll
        for (int j = 0; j < 4; j++)
#pragma unroll
            for (int t = 0; t < 4; t++) acc[i][j][t] = 0.f;

    const int a_row = wm * 64 + (lane & 15);
    const int a_koff = (lane >> 4) * 16;
    const int b_row4 = wn * 32 + ((lane >> 4) & 1) * 8 + (lane & 7);
    const int b_koff4 = ((lane >> 3) & 1) * 16;

    stage_issue(sb0, tid, Ahi + row0 * CC, Alo + row0 * CC, Bhi + boff, Blo + boff);
    stage_issue(sb0 + STAGEB, tid, Ahi + row0 * CC + KCH, Alo + row0 * CC + KCH,
                Bhi + boff + KCH, Blo + boff + KCH);

    for (int ch = 0; ch < 16; ch++) {
        const int cur = ch & 1;
        if (ch < 15) asm volatile("cp.async.wait_group 1;" ::: "memory");
        else         asm volatile("cp.async.wait_group 0;" ::: "memory");
        __syncthreads();

        const uint32_t base = sb0 + cur * STAGEB;
        const uint32_t aHs = base, aLs = base + MATB;
        const uint32_t bHs = base + 2 * MATB, bLs = base + 3 * MATB;
#pragma unroll
        for (int ks = 0; ks < 2; ks++) {
            const int kb = ks * 32;
            uint32_t ah[4][4], al[4][4], bh[4][2], bl[4][2];
#pragma unroll
            for (int i = 0; i < 4; i++) {
                uint32_t ra = (a_row + i * 16) * ROWB + kb + a_koff;
                ldm_x4(ah[i], aHs + ra);
                ldm_x4(al[i], aLs + ra);
            }
#pragma unroll
            for (int jp = 0; jp < 2; jp++) {
                uint32_t rb = (b_row4 + jp * 16) * ROWB + kb + b_koff4;
                uint32_t t4[4];
                ldm_x4(t4, bHs + rb);
                bh[jp * 2][0] = t4[0]; bh[jp * 2][1] = t4[1];
                bh[jp * 2 + 1][0] = t4[2]; bh[jp * 2 + 1][1] = t4[3];
                ldm_x4(t4, bLs + rb);
                bl[jp * 2][0] = t4[0]; bl[jp * 2][1] = t4[1];
                bl[jp * 2 + 1][0] = t4[2]; bl[jp * 2 + 1][1] = t4[3];
            }
#pragma unroll
            for (int i = 0; i < 4; i++)
#pragma unroll
                for (int j = 0; j < 4; j++) {
                    mma16816(acc[i][j], ah[i], bh[j]);
                    mma16816(acc[i][j], ah[i], bl[j]);
                    mma16816(acc[i][j], al[i], bh[j]);
                }
        }
        __syncthreads();
        if (ch + 2 < 16) {
            const int k0 = (ch + 2) * KCH;
            stage_issue(base, tid, Ahi + row0 * CC + k0, Alo + row0 * CC + k0,
                        Bhi + boff + k0, Blo + boff + k0);
        }
    }

    // ---- epilogue ----
    const int mrow = wm * 64 + (lane >> 2);
    const int mcol = wn * 32 + (lane & 3) * 2;

#pragma unroll
    for (int i = 0; i < 4; i++) {
#pragma unroll
        for (int half = 0; half < 2; half++) {
            size_t r = row0 + mrow + i * 16 + half * 8;
            size_t base = r * CC + n0 + mcol;
#pragma unroll
            for (int j = 0; j < 4; j++) {
                float2 v2;
                v2.x = acc[i][j][half * 2 + 0];
                v2.y = acc[i][j][half * 2 + 1];
                size_t off = base + j * 8;
                if (MODE == 1) {
                    float2 iv = *(const float2*)(illu + off);
                    *(float2*)(C2 + off) = v2;
                    uint32_t h, l;
                    cvt2(v2.x * iv.x, v2.y * iv.y, h, l);
                    ((uint32_t*)Vhi)[off >> 1] = h;
                    ((uint32_t*)Vlo)[off >> 1] = l;
                } else {
                    float2 bv = *(const float2*)(bias + n0 + mcol + j * 8);
                    v2.x += bv.x; v2.y += bv.y;
                    *(float2*)(C + off) = v2;
                }
            }
        }
    }
}

// =================== 1-term bf16 GEMM for Q/K (hi-only) ====================
// O^T[b][col][row] = bf16( A_hi[M,512] @ B_hi[512,512]^T ), hi only output.
// Also emits per-CTA column sum-of-squares partials (for the L2 norms).
#define STAGE1B (2 * MATB)         // 20480
#define GEMM1_SMEM (2 * STAGE1B)   // 40960

__device__ __forceinline__ void stage_issue1(
    uint32_t sb, int tid, const bf16* aHi, const bf16* bHi)
{
    const bf16* g[2] = {aHi, bHi};
#pragma unroll
    for (int m = 0; m < 2; m++) {
#pragma unroll
        for (int it = 0; it < 2; it++) {
            int u = tid + it * 256;
            int r = u >> 2, seg = u & 3;
            cp16(sb + m * MATB + r * ROWB + seg * 16,
                 g[m] + (size_t)r * CC + seg * 8);
        }
    }
    asm volatile("cp.async.commit_group;" ::: "memory");
}

__global__ void __launch_bounds__(256, 2) gemm_1t(
    const bf16* __restrict__ Ahi, const bf16* __restrict__ Bhi,
    bf16* __restrict__ Ohi, float* __restrict__ npart)
{
    extern __shared__ char smem[];
    const uint32_t sb0 = s2u(smem);
    const int tid = threadIdx.x;
    const int wid = tid >> 5, lane = tid & 31;
    const int wm = wid & 1, wn = wid >> 1;

    const size_t row0 = (size_t)blockIdx.y * 128;
    const int n0 = blockIdx.x * 128;
    const size_t boff = (size_t)n0 * CC;

    float acc[4][4][4];
#pragma unroll
    for (int i = 0; i < 4; i++)
#pragma unroll
        for (int j = 0; j < 4; j++)
#pragma unroll
            for (int t = 0; t < 4; t++) acc[i][j][t] = 0.f;

    const int a_row = wm * 64 + (lane & 15);
    const int a_koff = (lane >> 4) * 16;
    const int b_row4 = wn * 32 + ((lane >> 4) & 1) * 8 + (lane & 7);
    const int b_koff4 = ((lane >> 3) & 1) * 16;

    stage_issue1(sb0, tid, Ahi + row0 * CC, Bhi + boff);
    stage_issue1(sb0 + STAGE1B, tid, Ahi + row0 * CC + KCH, Bhi + boff + KCH);

    for (int ch = 0; ch < 16; ch++) {
        const int cur = ch & 1;
        if (ch < 15) asm volatile("cp.async.wait_group 1;" ::: "memory");
        else         asm volatile("cp.async.wait_group 0;" ::: "memory");
        __syncthreads();

        const uint32_t base = sb0 + cur * STAGE1B;
        const uint32_t aHs = base, bHs = base + MATB;
#pragma unroll
        for (int ks = 0; ks < 2; ks++) {
            const int kb = ks * 32;
            uint32_t ah[4][4], bh[4][2];
#pragma unroll
            for (int i = 0; i < 4; i++) {
                uint32_t ra = (a_row + i * 16) * ROWB + kb + a_koff;
                ldm_x4(ah[i], aHs + ra);
            }
#pragma unroll
            for (int jp = 0; jp < 2; jp++) {
                uint32_t rb = (b_row4 + jp * 16) * ROWB + kb + b_koff4;
                uint32_t t4[4];
                ldm_x4(t4, bHs + rb);
                bh[jp * 2][0] = t4[0]; bh[jp * 2][1] = t4[1];
                bh[jp * 2 + 1][0] = t4[2]; bh[jp * 2 + 1][1] = t4[3];
            }
#pragma unroll
            for (int i = 0; i < 4; i++)
#pragma unroll
                for (int j = 0; j < 4; j++)
                    mma16816(acc[i][j], ah[i], bh[j]);
        }
        __syncthreads();
        if (ch + 2 < 16) {
            const int k0 = (ch + 2) * KCH;
            stage_issue1(base, tid, Ahi + row0 * CC + k0, Bhi + boff + k0);
        }
    }

    // ---- epilogue 1: transposed bf16 hi output via smem transpose ----
    const int mrow = wm * 64 + (lane >> 2);
    const int mcol = wn * 32 + (lane & 3) * 2;

    float ss[8];
#pragma unroll
    for (int t = 0; t < 8; t++) ss[t] = 0.f;

    uint16_t* shh = (uint16_t*)smem;              // [128 cols][130]
    __syncthreads();
#pragma unroll
    for (int i = 0; i < 4; i++)
#pragma unroll
        for (int half = 0; half < 2; half++) {
            int row = mrow + i * 16 + half * 8;
#pragma unroll
            for (int j = 0; j < 4; j++) {
                int col = mcol + j * 8;
                float a0 = acc[i][j][half * 2 + 0];
                float a1 = acc[i][j][half * 2 + 1];
                ss[j * 2 + 0] += a0 * a0;
                ss[j * 2 + 1] += a1 * a1;
                uint32_t h = packbf(a0, a1);
                shh[col * 130 + row] = (uint16_t)h;
                shh[(col + 1) * 130 + row] = (uint16_t)(h >> 16);
            }
        }
    __syncthreads();
    const int b = (int)(blockIdx.y >> 7);
    const size_t nl0 = (size_t)(blockIdx.y & 127) * 128;
    uint32_t* dh = (uint32_t*)Ohi;
#pragma unroll
    for (int it = 0; it < 32; it++) {
        int c = it * 4 + (tid >> 6);
        int w = tid & 63;
        uint32_t hv = *(uint32_t*)(&shh[c * 130 + 2 * w]);
        size_t idx = ((((size_t)b * CC + n0 + c) * NTOK + nl0) >> 1) + w;
        dh[idx] = hv;
    }

    // ---- epilogue 2: per-CTA column sumsq partials ----
    __syncthreads();
    float* sred = (float*)smem;                  // [128 cols][16 contributors]
#pragma unroll
    for (int j = 0; j < 4; j++)
#pragma unroll
        for (int par = 0; par < 2; par++) {
            int col = mcol + j * 8 + par;
            sred[col * 16 + wm * 8 + (lane >> 2)] = ss[j * 2 + par];
        }
    __syncthreads();
    if (tid < 128) {
        float s = 0.f;
#pragma unroll
        for (int t = 0; t < 16; t++) s += sred[tid * 16 + t];
        int rb = (int)(blockIdx.y & 127);
        npart[((size_t)(b * 128 + rb)) * CC + n0 + tid] = s;
    }
}

// ------------- reduce column-sumsq partials -> inverse norms ---------------
__global__ void norm_reduce(const float* __restrict__ nq, const float* __restrict__ nk,
                            float* __restrict__ iq, float* __restrict__ ik)
{
    const int b = blockIdx.x;
    const int c = threadIdx.x;     // 512 threads
    float sq = 0.f, sk = 0.f;
    for (int rb = 0; rb < 128; rb++) {
        sq += nq[((size_t)(b * 128 + rb)) * CC + c];
        sk += nk[((size_t)(b * 128 + rb)) * CC + c];
    }
    iq[b * CC + c] = 1.f / fmaxf(sqrtf(sq), 1e-12f);
    ik[b * CC + c] = 1.f / fmaxf(sqrtf(sk), 1e-12f);
}

// ------------- Gram via mma with direct-LDG fragments (1-term hi) ----------
__global__ void __launch_bounds__(256) gram_mma(
    const bf16* __restrict__ KThi, const bf16* __restrict__ QThi,
    float* __restrict__ part)
{
    const int h = blockIdx.x, b = blockIdx.y, s = blockIdx.z;
    const int wid = threadIdx.x >> 5, lane = threadIdx.x & 31;
    const int nbase = s * (NTOK / GSPLIT) + wid * 256;

    const size_t rowbase = ((size_t)b * CC + h * DHEAD) * NTOK;
    const bf16* Kh = KThi + rowbase;
    const bf16* Qh = QThi + rowbase;

    float acc[4][8][4];
#pragma unroll
    for (int i = 0; i < 4; i++)
#pragma unroll
        for (int j = 0; j < 8; j++)
#pragma unroll
            for (int t = 0; t < 4; t++) acc[i][j][t] = 0.f;

    const int rsel = lane >> 2;
    const int csel = (lane & 3) * 2;

    for (int step = 0; step < 16; step++) {
        const int nb = nbase + step * 16 + csel;
        uint32_t ah[4][4];
#pragma unroll
        for (int mt = 0; mt < 4; mt++) {
            const size_t r0 = (size_t)(mt * 16 + rsel) * NTOK;
            const size_t r8 = r0 + 8 * NTOK;
            ah[mt][0] = *(const uint32_t*)(Kh + r0 + nb);
            ah[mt][1] = *(const uint32_t*)(Kh + r8 + nb);
            ah[mt][2] = *(const uint32_t*)(Kh + r0 + nb + 8);
            ah[mt][3] = *(const uint32_t*)(Kh + r8 + nb + 8);
        }
#pragma unroll
        for (int nt = 0; nt < 8; nt++) {
            const size_t q0 = (size_t)(nt * 8 + rsel) * NTOK;
            uint32_t bh[2];
            bh[0] = *(const uint32_t*)(Qh + q0 + nb);
            bh[1] = *(const uint32_t*)(Qh + q0 + nb + 8);
#pragma unroll
            for (int mt = 0; mt < 4; mt++)
                mma16816(acc[mt][nt], ah[mt], bh);
        }
    }

    const int sp = s * 8 + wid;
    float* dst = part + (((size_t)sp * BB + b) * NHEAD + h) * 4096;
#pragma unroll
    for (int mt = 0; mt < 4; mt++)
#pragma unroll
        for (int nt = 0; nt < 8; nt++) {
            int r = mt * 16 + rsel, c = nt * 8 + csel;
            dst[r * 64 + c]           = acc[mt][nt][0];
            dst[r * 64 + c + 1]       = acc[mt][nt][1];
            dst[(r + 8) * 64 + c]     = acc[mt][nt][2];
            dst[(r + 8) * 64 + c + 1] = acc[mt][nt][3];
        }
}

// ------------- softmax over e ----------------------------------------------
__global__ void softmax_kernel(const float* __restrict__ part,
                               const float* __restrict__ iq,
                               const float* __restrict__ ik,
                               const float* __restrict__ rescale,
                               float* __restrict__ attn)
{
    int bh = blockIdx.x;
    int b = bh / NHEAD, h = bh % NHEAD;
    int d = threadIdx.x;

    __shared__ float iq_s[64];
    iq_s[d] = iq[b * CC + h * DHEAD + d];
    float ik_d = ik[b * CC + h * DHEAD + d];
    float resc = rescale[h];
    __syncthreads();

    float row[64];
#pragma unroll
    for (int e = 0; e < 64; e++) row[e] = 0.f;
    for (int sp = 0; sp < GS_TOT; sp++) {
        const float* p = part + (((size_t)sp * BB + b) * NHEAD + h) * 4096 + d * 64;
#pragma unroll 8
        for (int e = 0; e < 64; e++) row[e] += p[e];
    }
    float m = -1e30f;
#pragma unroll
    for (int e = 0; e < 64; e++) {
        row[e] = row[e] * ik_d * iq_s[e] * resc;
        m = fmaxf(m, row[e]);
    }
    float sum = 0.f;
#pragma unroll
    for (int e = 0; e < 64; e++) {
        row[e] = __expf(row[e] - m);
        sum += row[e];
    }
    float inv = 1.f / sum;
    float* dst = attn + ((size_t)(b * NHEAD + h)) * 4096 + d * 64;
#pragma unroll
    for (int e = 0; e < 64; e++) dst[e] = row[e] * inv;
}

// ------------- Weff[b][h*64+e][j] = sum_d attn[b,h,d,e] * Wp[h*64+d][j] -----
__global__ void weff_kernel(const float* __restrict__ attn,
                            const float* __restrict__ Wp,
                            float* __restrict__ weff)
{
    int eg = blockIdx.x;
    int b = blockIdx.y;
    int tid = threadIdx.x;
    int h = eg >> 6, e = eg & 63;

    __shared__ float a_s[64];
    if (tid < 64) a_s[tid] = attn[((size_t)(b * NHEAD + h) * 64 + tid) * 64 + e];
    __syncthreads();

    for (int j = tid; j < CC; j += 256) {
        float acc = 0.f;
#pragma unroll
        for (int d = 0; d < 64; d++)
            acc += a_s[d] * Wp[(size_t)(h * 64 + d) * CC + j];
        weff[((size_t)b * CC + eg) * CC + j] = acc;
    }
}

// ------------- fused dwconv3 -> GELU -> dwconv3, smem-staged input ---------
// 16 channels per block; input tile 20x20 in smem, conv1 tile 18x18, out 16x16.
__global__ void __launch_bounds__(256) dwconv_fused(
    const float* __restrict__ in, const float* __restrict__ w1,
    const float* __restrict__ w2, float* __restrict__ out)
{
    __shared__ float sin_[20 * 20 * 16];   // 25.6 KB
    __shared__ float t[18 * 18 * 16];      // 20.7 KB
    const int chb = (blockIdx.z & 31) * 16;
    const int b = blockIdx.z >> 5;
    const int x0 = blockIdx.x * 16, y0 = blockIdx.y * 16;
    const int ch = threadIdx.x & 15;
    const int sp = threadIdx.x >> 4;       // 16 spatial workers

    // stage input 20x20x16 tile (origin y0-2, x0-2), zero OOB
    for (int p = threadIdx.x; p < 20 * 20 * 16; p += 256) {
        int c2 = p & 15;
        int xx = (p >> 4) % 20;
        int yy = p / (20 * 16);
        int gy = y0 + yy - 2, gx = x0 + xx - 2;
        float v = 0.f;
        if (gy >= 0 && gy < HH && gx >= 0 && gx < WW)
            v = in[(((size_t)b * HH + gy) * WW + gx) * CC + chb + c2];
        sin_[p] = v;
    }
    __syncthreads();

    float wv[9];
#pragma unroll
    for (int k = 0; k < 9; k++) wv[k] = w1[(chb + ch) * 9 + k];

    // conv1 + gelu on 18x18 halo tile (abs origin y0-1, x0-1)
    for (int p = sp; p < 324; p += 16) {
        int ly = p / 18, lx = p - ly * 18;
        int oy = y0 + ly - 1, ox = x0 + lx - 1;
        float val = 0.f;
        if (oy >= 0 && oy < HH && ox >= 0 && ox < WW) {
            float acc = 0.f;
#pragma unroll
            for (int dy = 0; dy < 3; dy++)
#pragma unroll
                for (int dx = 0; dx < 3; dx++)
                    acc += sin_[((ly + dy) * 20 + lx + dx) * 16 + ch] * wv[dy * 3 + dx];
            val = 0.5f * acc * (1.f + erff(acc * 0.70710678118654752f));
        }
        t[p * 16 + ch] = val;
    }
    __syncthreads();

#pragma unroll
    for (int k = 0; k < 9; k++) wv[k] = w2[(chb + ch) * 9 + k];

    // conv2 on 16x16 interior, accumulate into out
    for (int p = sp; p < 256; p += 16) {
        int ly = p >> 4, lx = p & 15;
        float acc = 0.f;
#pragma unroll
        for (int dy = 0; dy < 3; dy++)
#pragma unroll
            for (int dx = 0; dx < 3; dx++)
                acc += t[((ly + dy) * 18 + lx + dx) * 16 + ch] * wv[dy * 3 + dx];
        size_t o = (((size_t)b * HH + y0 + ly) * WW + x0 + lx) * CC + chb + ch;
        out[o] += acc;
    }
}

// ---------------------------------------------------------------------------
extern "C" void kernel_launch(void* const* d_in, const int* in_sizes, int n_in,
                              void* d_out, int out_size)
{
    const float* x    = (const float*)d_in[0];
    const float* illu = (const float*)d_in[1];
    const float* Wq   = (const float*)d_in[2];
    const float* Wk   = (const float*)d_in[3];
    const float* Wv   = (const float*)d_in[4];
    const float* resc = (const float*)d_in[5];
    const float* Wp   = (const float*)d_in[6];
    const float* bp   = (const float*)d_in[7];
    const float* c1w  = (const float*)d_in[8];
    const float* c2w  = (const float*)d_in[9];
    float* out = (float*)d_out;

    float *vinp, *weff, *nq, *nk, *iq, *ik, *gp, *attn;
    bf16 *xhi, *xlo, *vhi, *vlo, *wThi, *wTlo, *wfhi, *wflo;
    bf16 *qthi, *kthi;
    cudaGetSymbolAddress((void**)&vinp, g_vinp);
    cudaGetSymbolAddress((void**)&weff, g_weff);
    cudaGetSymbolAddress((void**)&nq, g_nq);
    cudaGetSymbolAddress((void**)&nk, g_nk);
    cudaGetSymbolAddress((void**)&iq, g_invq);
    cudaGetSymbolAddress((void**)&ik, g_invk);
    cudaGetSymbolAddress((void**)&gp, g_gpart);
    cudaGetSymbolAddress((void**)&attn, g_attn);
    cudaGetSymbolAddress((void**)&xhi, g_xhi);
    cudaGetSymbolAddress((void**)&xlo, g_xlo);
    cudaGetSymbolAddress((void**)&vhi, g_vhi);
    cudaGetSymbolAddress((void**)&vlo, g_vlo);
    cudaGetSymbolAddress((void**)&wThi, g_wThi);
    cudaGetSymbolAddress((void**)&wTlo, g_wTlo);
    cudaGetSymbolAddress((void**)&wfhi, g_wfhi);
    cudaGetSymbolAddress((void**)&wflo, g_wflo);
    cudaGetSymbolAddress((void**)&qthi, g_qthi);
    cudaGetSymbolAddress((void**)&kthi, g_kthi);

    cudaFuncSetAttribute(gemm_bf<1>, cudaFuncAttributeMaxDynamicSharedMemorySize, GEMM_SMEM);
    cudaFuncSetAttribute(gemm_bf<2>, cudaFuncAttributeMaxDynamicSharedMemorySize, GEMM_SMEM);
    cudaFuncSetAttribute(gemm_1t, cudaFuncAttributeMaxDynamicSharedMemorySize, GEMM1_SMEM);

    // 0) conversions: x -> bf16 hi/lo; weights -> transposed bf16 hi/lo
    cvt_x<<<(int)((size_t)MTOT * CC / (256 * 8)), 256>>>(x, xhi, xlo);
    dim3 tb(32, 8);
    tcvt<<<dim3(8, 16, 1), tb>>>(Wq, wThi, wTlo, CC, 0, 0);
    tcvt<<<dim3(8, 16, 1), tb>>>(Wk, wThi + CC * CC, wTlo + CC * CC, CC, 0, 0);
    tcvt<<<dim3(8, 16, 1), tb>>>(Wv, wThi + 2 * CC * CC, wTlo + 2 * CC * CC, CC, 0, 0);

    // 1) projections: q,k 1-term hi-only -> transposed (+ norm partials);
    //    v 3-term gated + raw
    dim3 gProj(CC / 128, MTOT / 128, 1);
    gemm_1t<<<gProj, 256, GEMM1_SMEM>>>(xhi, wThi, qthi, nq);
    gemm_1t<<<gProj, 256, GEMM1_SMEM>>>(xhi, wThi + CC * CC, kthi, nk);
    gemm_bf<1><<<gProj, 256, GEMM_SMEM>>>(xhi, xlo, wThi + 2 * CC * CC, wTlo + 2 * CC * CC,
        nullptr, vinp, vhi, vlo, illu, nullptr, 0, 0);

    // 2) reduce norm partials -> inverse norms
    norm_reduce<<<BB, CC>>>(nq, nk, iq, ik);

    // 3) gram on tensor pipe (1-term) + softmax
    gram_mma<<<dim3(NHEAD, BB, GSPLIT), 256>>>(kthi, qthi, gp);
    softmax_kernel<<<BB * NHEAD, 64>>>(gp, iq, ik, resc, attn);

    // 4) fold attention into Wp; transpose-convert to bf16 [n][k]
    weff_kernel<<<dim3(CC, BB), 256>>>(attn, Wp, weff);
    tcvt<<<dim3(8, 16, BB), tb>>>(weff, wfhi, wflo, CC,
        (size_t)CC * CC, (size_t)CC * CC);

    // 5) out_c = V @ Weff_b + bp (batched, 3-term)
    gemm_bf<2><<<dim3(CC / 128, NTOK / 128, BB), 256, GEMM_SMEM>>>(
        vhi, vlo, wfhi, wflo, out, nullptr, nullptr, nullptr, nullptr, bp,
        (size_t)NTOK, (size_t)CC * CC);

    // 6) positional branch: fused dwconv -> gelu -> dwconv, added to out
    dwconv_fused<<<dim3(WW / 16, HH / 16, BB * 32), 256>>>(vinp, c1w, c2w, out);
}

// round 13
// speedup vs baseline: 1.9746x; 1.0328x over previous
#include <cuda_runtime.h>
#include <cuda_bf16.h>
#include <math.h>
#include <stdint.h>

// Problem constants
#define BB 4
#define HH 128
#define WW 128
#define CC 512
#define NTOK 16384            // H*W
#define NHEAD 8
#define DHEAD 64
#define MTOT (BB*NTOK)        // 65536
#define GSPLIT 8
#define GS_TOT 64

typedef __nv_bfloat16 bf16;

// ---------------- scratch (device globals; no runtime allocation) ----------
static __device__ float g_vinp[(size_t)MTOT * CC];   // raw x@Wv (conv branch)
static __device__ float g_conv[(size_t)MTOT * CC];   // conv branch output
static __device__ float g_weff[(size_t)BB * CC * CC];

static __device__ __align__(16) bf16 g_xhi[(size_t)MTOT * CC];
static __device__ __align__(16) bf16 g_xlo[(size_t)MTOT * CC];
static __device__ __align__(16) bf16 g_vhi[(size_t)MTOT * CC];
static __device__ __align__(16) bf16 g_vlo[(size_t)MTOT * CC];
static __device__ __align__(16) bf16 g_wThi[3 * CC * CC];
static __device__ __align__(16) bf16 g_wTlo[3 * CC * CC];
static __device__ __align__(16) bf16 g_wfhi[(size_t)BB * CC * CC];
static __device__ __align__(16) bf16 g_wflo[(size_t)BB * CC * CC];
static __device__ __align__(16) bf16 g_qkt[2 * (size_t)BB * CC * NTOK]; // q^T,k^T hi

static __device__ float g_nqk[2 * (size_t)BB * 128 * CC];  // colsumsq partials
static __device__ float g_invq[BB * CC];
static __device__ float g_invk[BB * CC];
static __device__ float g_gpart[(size_t)GS_TOT * BB * NHEAD * DHEAD * DHEAD];
static __device__ float g_attn[(size_t)BB * NHEAD * DHEAD * DHEAD];

// =================== helpers ==============================================
__device__ __forceinline__ uint32_t s2u(const void* p) {
    uint32_t a;
    asm("{ .reg .u64 t; cvta.to.shared.u64 t, %1; cvt.u32.u64 %0, t; }"
        : "=r"(a) : "l"(p));
    return a;
}

// split 2 floats -> packed bf16 hi pair and lo pair (low half = first arg)
__device__ __forceinline__ void cvt2(float a, float b, uint32_t& h, uint32_t& l) {
    uint32_t hp;
    asm("cvt.rn.bf16x2.f32 %0, %1, %2;" : "=r"(hp) : "f"(b), "f"(a));
    float ah = __uint_as_float(hp << 16);
    float bh = __uint_as_float(hp & 0xFFFF0000u);
    float al = a - ah;
    float bl = b - bh;
    uint32_t lp;
    asm("cvt.rn.bf16x2.f32 %0, %1, %2;" : "=r"(lp) : "f"(bl), "f"(al));
    h = hp; l = lp;
}

__device__ __forceinline__ uint32_t packbf(float a, float b) {
    uint32_t hp;
    asm("cvt.rn.bf16x2.f32 %0, %1, %2;" : "=r"(hp) : "f"(b), "f"(a));
    return hp;
}

__device__ __forceinline__ void split1(float f, uint16_t& h, uint16_t& l) {
    uint32_t hp;
    asm("cvt.rn.bf16x2.f32 %0, %1, %2;" : "=r"(hp) : "f"(0.f), "f"(f));
    float hf = __uint_as_float(hp << 16);
    float lf = f - hf;
    uint32_t lp;
    asm("cvt.rn.bf16x2.f32 %0, %1, %2;" : "=r"(lp) : "f"(0.f), "f"(lf));
    h = (uint16_t)hp; l = (uint16_t)lp;
}

__device__ __forceinline__ void ldm_x4(uint32_t* r, uint32_t addr) {
    asm volatile("ldmatrix.sync.aligned.m8n8.x4.shared.b16 {%0,%1,%2,%3}, [%4];"
                 : "=r"(r[0]), "=r"(r[1]), "=r"(r[2]), "=r"(r[3]) : "r"(addr));
}
__device__ __forceinline__ void mma16816(float* c, const uint32_t* a, const uint32_t* b) {
    asm volatile(
        "mma.sync.aligned.m16n8k16.row.col.f32.bf16.bf16.f32 "
        "{%0,%1,%2,%3}, {%4,%5,%6,%7}, {%8,%9}, {%0,%1,%2,%3};"
        : "+f"(c[0]), "+f"(c[1]), "+f"(c[2]), "+f"(c[3])
        : "r"(a[0]), "r"(a[1]), "r"(a[2]), "r"(a[3]), "r"(b[0]), "r"(b[1]));
}
__device__ __forceinline__ void cp16(uint32_t dst, const void* src) {
    asm volatile("cp.async.cg.shared.global [%0], [%1], 16;" :: "r"(dst), "l"(src));
}

// =================== conversion kernels ====================================
__global__ void cvt_x(const float* __restrict__ x, bf16* __restrict__ xhi,
                      bf16* __restrict__ xlo)
{
    size_t g = ((size_t)blockIdx.x * 256 + threadIdx.x);
    const float4* p = (const float4*)(x + g * 8);
    float4 a = p[0], b = p[1];
    uint4 h, l;
    cvt2(a.x, a.y, h.x, l.x); cvt2(a.z, a.w, h.y, l.y);
    cvt2(b.x, b.y, h.z, l.z); cvt2(b.z, b.w, h.w, l.w);
    ((uint4*)xhi)[g] = h;
    ((uint4*)xlo)[g] = l;
}

// transpose + convert: src fp32 [R][512] (batched) -> dst bf16 [512][R] hi/lo
__global__ void tcvt(const float* __restrict__ src, bf16* __restrict__ dhi,
                     bf16* __restrict__ dlo, int R, size_t sStride, size_t dStride)
{
    __shared__ uint16_t shh[32][65];
    __shared__ uint16_t shl[32][65];
    int z = blockIdx.z;
    const float* s = src + (size_t)z * sStride;
    int c = blockIdx.y * 32 + threadIdx.x;
    int nb = blockIdx.x * 64;
#pragma unroll
    for (int i = 0; i < 8; i++) {
        int n = threadIdx.y + i * 8;
        float f = s[(size_t)(nb + n) * CC + c];
        uint16_t h, l;
        split1(f, h, l);
        shh[threadIdx.x][n] = h;
        shl[threadIdx.x][n] = l;
    }
    __syncthreads();
#pragma unroll
    for (int i = 0; i < 4; i++) {
        int cl = threadIdx.y + i * 8;
        int row = blockIdx.y * 32 + cl;
        size_t u32idx = ((size_t)row * R + nb) >> 1;
        uint32_t h = (uint32_t)shh[cl][threadIdx.x * 2] |
                     ((uint32_t)shh[cl][threadIdx.x * 2 + 1] << 16);
        uint32_t l = (uint32_t)shl[cl][threadIdx.x * 2] |
                     ((uint32_t)shl[cl][threadIdx.x * 2 + 1] << 16);
        ((uint32_t*)(dhi + (size_t)z * dStride))[u32idx + threadIdx.x] = h;
        ((uint32_t*)(dlo + (size_t)z * dStride))[u32idx + threadIdx.x] = l;
    }
}

// =================== pipelined bf16 GEMM (3-term) ==========================
// MODE 1: C2 = raw fp32; Vhi/Vlo = bf16 split of raw*illu
// MODE 2: C = A@B + bias + Cin (conv result already in C's buffer? no: C += from CV)
#define KCH 32
#define ROWB 80
#define MATB (128 * ROWB)        // 10240
#define STAGEB (4 * MATB)        // 40960
#define GEMM_SMEM (2 * STAGEB)   // 81920

__device__ __forceinline__ void stage_issue(
    uint32_t sb, int tid,
    const bf16* aHi, const bf16* aLo, const bf16* bHi, const bf16* bLo)
{
    const bf16* g[4] = {aHi, aLo, bHi, bLo};
#pragma unroll
    for (int m = 0; m < 4; m++) {
#pragma unroll
        for (int it = 0; it < 2; it++) {
            int u = tid + it * 256;
            int r = u >> 2, seg = u & 3;
            cp16(sb + m * MATB + r * ROWB + seg * 16,
                 g[m] + (size_t)r * CC + seg * 8);
        }
    }
    asm volatile("cp.async.commit_group;" ::: "memory");
}

template <int MODE>
__global__ void __launch_bounds__(256, 2) gemm_bf(
    const bf16* __restrict__ Ahi, const bf16* __restrict__ Alo,
    const bf16* __restrict__ Bhi, const bf16* __restrict__ Blo,
    float* __restrict__ C, float* __restrict__ C2,
    bf16* __restrict__ Vhi, bf16* __restrict__ Vlo,
    const float* __restrict__ illu, const float* __restrict__ bias,
    size_t zRow, size_t sB)
{
    extern __shared__ char smem[];
    const uint32_t sb0 = s2u(smem);
    const int tid = threadIdx.x;
    const int wid = tid >> 5, lane = tid & 31;
    const int wm = wid & 1, wn = wid >> 1;

    const size_t row0 = (size_t)blockIdx.y * 128 + (size_t)blockIdx.z * zRow;
    const int n0 = blockIdx.x * 128;
    const size_t boff = (size_t)blockIdx.z * sB + (size_t)n0 * CC;

    float acc[4][4][4];
#pragma unroll
    for (int i = 0; i < 4; i++)
#pragma unroll
        for (int j = 0; j < 4; j++)
#pragma unroll
            for (int t = 0; t < 4; t++) acc[i][j][t] = 0.f;

    const int a_row = wm * 64 + (lane & 15);
    const int a_koff = (lane >> 4) * 16;
    const int b_row4 = wn * 32 + ((lane >> 4) & 1) * 8 + (lane & 7);
    const int b_koff4 = ((lane >> 3) & 1) * 16;

    stage_issue(sb0, tid, Ahi + row0 * CC, Alo + row0 * CC, Bhi + boff, Blo + boff);
    stage_issue(sb0 + STAGEB, tid, Ahi + row0 * CC + KCH, Alo + row0 * CC + KCH,
                Bhi + boff + KCH, Blo + boff + KCH);

    for (int ch = 0; ch < 16; ch++) {
        const int cur = ch & 1;
        if (ch < 15) asm volatile("cp.async.wait_group 1;" ::: "memory");
        else         asm volatile("cp.async.wait_group 0;" ::: "memory");
        __syncthreads();

        const uint32_t base = sb0 + cur * STAGEB;
        const uint32_t aHs = base, aLs = base + MATB;
        const uint32_t bHs = base + 2 * MATB, bLs = base + 3 * MATB;
#pragma unroll
        for (int ks = 0; ks < 2; ks++) {
            const int kb = ks * 32;
            uint32_t ah[4][4], al[4][4], bh[4][2], bl[4][2];
#pragma unroll
            for (int i = 0; i < 4; i++) {
                uint32_t ra = (a_row + i * 16) * ROWB + kb + a_koff;
                ldm_x4(ah[i], aHs + ra);
                ldm_x4(al[i], aLs + ra);
            }
#pragma unroll
            for (int jp = 0; jp < 2; jp++) {
                uint32_t rb = (b_row4 + jp * 16) * ROWB + kb + b_koff4;
                uint32_t t4[4];
                ldm_x4(t4, bHs + rb);
                bh[jp * 2][0] = t4[0]; bh[jp * 2][1] = t4[1];
                bh[jp * 2 + 1][0] = t4[2]; bh[jp * 2 + 1][1] = t4[3];
                ldm_x4(t4, bLs + rb);
                bl[jp * 2][0] = t4[0]; bl[jp * 2][1] = t4[1];
                bl[jp * 2 + 1][0] = t4[2]; bl[jp * 2 + 1][1] = t4[3];
            }
#pragma unroll
            for (int i = 0; i < 4; i++)
#pragma unroll
                for (int j = 0; j < 4; j++) {
                    mma16816(acc[i][j], ah[i], bh[j]);
                    mma16816(acc[i][j], ah[i], bl[j]);
                    mma16816(acc[i][j], al[i], bh[j]);
                }
        }
        __syncthreads();
        if (ch + 2 < 16) {
            const int k0 = (ch + 2) * KCH;
            stage_issue(base, tid, Ahi + row0 * CC + k0, Alo + row0 * CC + k0,
                        Bhi + boff + k0, Blo + boff + k0);
        }
    }

    // ---- epilogue ----
    const int mrow = wm * 64 + (lane >> 2);
    const int mcol = wn * 32 + (lane & 3) * 2;

#pragma unroll
    for (int i = 0; i < 4; i++) {
#pragma unroll
        for (int half = 0; half < 2; half++) {
            size_t r = row0 + mrow + i * 16 + half * 8;
            size_t base = r * CC + n0 + mcol;
#pragma unroll
            for (int j = 0; j < 4; j++) {
                float2 v2;
                v2.x = acc[i][j][half * 2 + 0];
                v2.y = acc[i][j][half * 2 + 1];
                size_t off = base + j * 8;
                if (MODE == 1) {
                    float2 iv = *(const float2*)(illu + off);
                    *(float2*)(C2 + off) = v2;
                    uint32_t h, l;
                    cvt2(v2.x * iv.x, v2.y * iv.y, h, l);
                    ((uint32_t*)Vhi)[off >> 1] = h;
                    ((uint32_t*)Vlo)[off >> 1] = l;
                } else {
                    float2 bv = *(const float2*)(bias + n0 + mcol + j * 8);
                    v2.x += bv.x; v2.y += bv.y;
                    *(float2*)(C + off) = v2;
                }
            }
        }
    }
}

// =================== 1-term bf16 GEMM for Q/K merged (hi-only) =============
// z=0: q; z=1: k. Transposed hi output + column sumsq partials.
#define STAGE1B (2 * MATB)         // 20480
#define GEMM1_SMEM (2 * STAGE1B)   // 40960

__device__ __forceinline__ void stage_issue1(
    uint32_t sb, int tid, const bf16* aHi, const bf16* bHi)
{
    const bf16* g[2] = {aHi, bHi};
#pragma unroll
    for (int m = 0; m < 2; m++) {
#pragma unroll
        for (int it = 0; it < 2; it++) {
            int u = tid + it * 256;
            int r = u >> 2, seg = u & 3;
            cp16(sb + m * MATB + r * ROWB + seg * 16,
                 g[m] + (size_t)r * CC + seg * 8);
        }
    }
    asm volatile("cp.async.commit_group;" ::: "memory");
}

__global__ void __launch_bounds__(256, 2) gemm_qk(
    const bf16* __restrict__ Ahi, const bf16* __restrict__ WThi,
    bf16* __restrict__ Oqk, float* __restrict__ npart)
{
    extern __shared__ char smem[];
    const uint32_t sb0 = s2u(smem);
    const int tid = threadIdx.x;
    const int wid = tid >> 5, lane = tid & 31;
    const int wm = wid & 1, wn = wid >> 1;
    const int z = blockIdx.z;

    const bf16* Bhi = WThi + (size_t)z * CC * CC;
    bf16* Ohi = Oqk + (size_t)z * BB * CC * NTOK;
    float* np = npart + (size_t)z * BB * 128 * CC;

    const size_t row0 = (size_t)blockIdx.y * 128;
    const int n0 = blockIdx.x * 128;
    const size_t boff = (size_t)n0 * CC;

    float acc[4][4][4];
#pragma unroll
    for (int i = 0; i < 4; i++)
#pragma unroll
        for (int j = 0; j < 4; j++)
#pragma unroll
            for (int t = 0; t < 4; t++) acc[i][j][t] = 0.f;

    const int a_row = wm * 64 + (lane & 15);
    const int a_koff = (lane >> 4) * 16;
    const int b_row4 = wn * 32 + ((lane >> 4) & 1) * 8 + (lane & 7);
    const int b_koff4 = ((lane >> 3) & 1) * 16;

    stage_issue1(sb0, tid, Ahi + row0 * CC, Bhi + boff);
    stage_issue1(sb0 + STAGE1B, tid, Ahi + row0 * CC + KCH, Bhi + boff + KCH);

    for (int ch = 0; ch < 16; ch++) {
        const int cur = ch & 1;
        if (ch < 15) asm volatile("cp.async.wait_group 1;" ::: "memory");
        else         asm volatile("cp.async.wait_group 0;" ::: "memory");
        __syncthreads();

        const uint32_t base = sb0 + cur * STAGE1B;
        const uint32_t aHs = base, bHs = base + MATB;
#pragma unroll
        for (int ks = 0; ks < 2; ks++) {
            const int kb = ks * 32;
            uint32_t ah[4][4], bh[4][2];
#pragma unroll
            for (int i = 0; i < 4; i++) {
                uint32_t ra = (a_row + i * 16) * ROWB + kb + a_koff;
                ldm_x4(ah[i], aHs + ra);
            }
#pragma unroll
            for (int jp = 0; jp < 2; jp++) {
                uint32_t rb = (b_row4 + jp * 16) * ROWB + kb + b_koff4;
                uint32_t t4[4];
                ldm_x4(t4, bHs + rb);
                bh[jp * 2][0] = t4[0]; bh[jp * 2][1] = t4[1];
                bh[jp * 2 + 1][0] = t4[2]; bh[jp * 2 + 1][1] = t4[3];
            }
#pragma unroll
            for (int i = 0; i < 4; i++)
#pragma unroll
                for (int j = 0; j < 4; j++)
                    mma16816(acc[i][j], ah[i], bh[j]);
        }
        __syncthreads();
        if (ch + 2 < 16) {
            const int k0 = (ch + 2) * KCH;
            stage_issue1(base, tid, Ahi + row0 * CC + k0, Bhi + boff + k0);
        }
    }

    // ---- epilogue 1: transposed bf16 hi output via smem transpose ----
    const int mrow = wm * 64 + (lane >> 2);
    const int mcol = wn * 32 + (lane & 3) * 2;

    float ss[8];
#pragma unroll
    for (int t = 0; t < 8; t++) ss[t] = 0.f;

    uint16_t* shh = (uint16_t*)smem;              // [128 cols][130]
    __syncthreads();
#pragma unroll
    for (int i = 0; i < 4; i++)
#pragma unroll
        for (int half = 0; half < 2; half++) {
            int row = mrow + i * 16 + half * 8;
#pragma unroll
            for (int j = 0; j < 4; j++) {
                int col = mcol + j * 8;
                float a0 = acc[i][j][half * 2 + 0];
                float a1 = acc[i][j][half * 2 + 1];
                ss[j * 2 + 0] += a0 * a0;
                ss[j * 2 + 1] += a1 * a1;
                uint32_t h = packbf(a0, a1);
                shh[col * 130 + row] = (uint16_t)h;
                shh[(col + 1) * 130 + row] = (uint16_t)(h >> 16);
            }
        }
    __syncthreads();
    const int b = (int)(blockIdx.y >> 7);
    const size_t nl0 = (size_t)(blockIdx.y & 127) * 128;
    uint32_t* dh = (uint32_t*)Ohi;
#pragma unroll
    for (int it = 0; it < 32; it++) {
        int c = it * 4 + (tid >> 6);
        int w = tid & 63;
        uint32_t hv = *(uint32_t*)(&shh[c * 130 + 2 * w]);
        size_t idx = ((((size_t)b * CC + n0 + c) * NTOK + nl0) >> 1) + w;
        dh[idx] = hv;
    }

    // ---- epilogue 2: per-CTA column sumsq partials ----
    __syncthreads();
    float* sred = (float*)smem;
#pragma unroll
    for (int j = 0; j < 4; j++)
#pragma unroll
        for (int par = 0; par < 2; par++) {
            int col = mcol + j * 8 + par;
            sred[col * 16 + wm * 8 + (lane >> 2)] = ss[j * 2 + par];
        }
    __syncthreads();
    if (tid < 128) {
        float s = 0.f;
#pragma unroll
        for (int t = 0; t < 16; t++) s += sred[tid * 16 + t];
        int rb = (int)(blockIdx.y & 127);
        np[((size_t)(b * 128 + rb)) * CC + n0 + tid] = s;
    }
}

// ------------- reduce column-sumsq partials -> inverse norms ---------------
__global__ void norm_reduce(const float* __restrict__ nqk,
                            float* __restrict__ iq, float* __restrict__ ik)
{
    const int b = blockIdx.x;
    const int c = threadIdx.x;     // 512 threads
    const float* nq = nqk;
    const float* nk = nqk + (size_t)BB * 128 * CC;
    float sq = 0.f, sk = 0.f;
    for (int rb = 0; rb < 128; rb++) {
        sq += nq[((size_t)(b * 128 + rb)) * CC + c];
        sk += nk[((size_t)(b * 128 + rb)) * CC + c];
    }
    iq[b * CC + c] = 1.f / fmaxf(sqrtf(sq), 1e-12f);
    ik[b * CC + c] = 1.f / fmaxf(sqrtf(sk), 1e-12f);
}

// ------------- Gram via mma with direct-LDG fragments (1-term hi) ----------
__global__ void __launch_bounds__(256) gram_mma(
    const bf16* __restrict__ KThi, const bf16* __restrict__ QThi,
    float* __restrict__ part)
{
    const int h = blockIdx.x, b = blockIdx.y, s = blockIdx.z;
    const int wid = threadIdx.x >> 5, lane = threadIdx.x & 31;
    const int nbase = s * (NTOK / GSPLIT) + wid * 256;

    const size_t rowbase = ((size_t)b * CC + h * DHEAD) * NTOK;
    const bf16* Kh = KThi + rowbase;
    const bf16* Qh = QThi + rowbase;

    float acc[4][8][4];
#pragma unroll
    for (int i = 0; i < 4; i++)
#pragma unroll
        for (int j = 0; j < 8; j++)
#pragma unroll
            for (int t = 0; t < 4; t++) acc[i][j][t] = 0.f;

    const int rsel = lane >> 2;
    const int csel = (lane & 3) * 2;

    for (int step = 0; step < 16; step++) {
        const int nb = nbase + step * 16 + csel;
        uint32_t ah[4][4];
#pragma unroll
        for (int mt = 0; mt < 4; mt++) {
            const size_t r0 = (size_t)(mt * 16 + rsel) * NTOK;
            const size_t r8 = r0 + 8 * NTOK;
            ah[mt][0] = *(const uint32_t*)(Kh + r0 + nb);
            ah[mt][1] = *(const uint32_t*)(Kh + r8 + nb);
            ah[mt][2] = *(const uint32_t*)(Kh + r0 + nb + 8);
            ah[mt][3] = *(const uint32_t*)(Kh + r8 + nb + 8);
        }
#pragma unroll
        for (int nt = 0; nt < 8; nt++) {
            const size_t q0 = (size_t)(nt * 8 + rsel) * NTOK;
            uint32_t bh[2];
            bh[0] = *(const uint32_t*)(Qh + q0 + nb);
            bh[1] = *(const uint32_t*)(Qh + q0 + nb + 8);
#pragma unroll
            for (int mt = 0; mt < 4; mt++)
                mma16816(acc[mt][nt], ah[mt], bh);
        }
    }

    const int sp = s * 8 + wid;
    float* dst = part + (((size_t)sp * BB + b) * NHEAD + h) * 4096;
#pragma unroll
    for (int mt = 0; mt < 4; mt++)
#pragma unroll
        for (int nt = 0; nt < 8; nt++) {
            int r = mt * 16 + rsel, c = nt * 8 + csel;
            dst[r * 64 + c]           = acc[mt][nt][0];
            dst[r * 64 + c + 1]       = acc[mt][nt][1];
            dst[(r + 8) * 64 + c]     = acc[mt][nt][2];
            dst[(r + 8) * 64 + c + 1] = acc[mt][nt][3];
        }
}

// ------------- softmax over e ----------------------------------------------
__global__ void softmax_kernel(const float* __restrict__ part,
                               const float* __restrict__ iq,
                               const float* __restrict__ ik,
                               const float* __restrict__ rescale,
                               float* __restrict__ attn)
{
    int bh = blockIdx.x;
    int b = bh / NHEAD, h = bh % NHEAD;
    int d = threadIdx.x;

    __shared__ float iq_s[64];
    iq_s[d] = iq[b * CC + h * DHEAD + d];
    float ik_d = ik[b * CC + h * DHEAD + d];
    float resc = rescale[h];
    __syncthreads();

    float row[64];
#pragma unroll
    for (int e = 0; e < 64; e++) row[e] = 0.f;
    for (int sp = 0; sp < GS_TOT; sp++) {
        const float* p = part + (((size_t)sp * BB + b) * NHEAD + h) * 4096 + d * 64;
#pragma unroll 8
        for (int e = 0; e < 64; e++) row[e] += p[e];
    }
    float m = -1e30f;
#pragma unroll
    for (int e = 0; e < 64; e++) {
        row[e] = row[e] * ik_d * iq_s[e] * resc;
        m = fmaxf(m, row[e]);
    }
    float sum = 0.f;
#pragma unroll
    for (int e = 0; e < 64; e++) {
        row[e] = __expf(row[e] - m);
        sum += row[e];
    }
    float inv = 1.f / sum;
    float* dst = attn + ((size_t)(b * NHEAD + h)) * 4096 + d * 64;
#pragma unroll
    for (int e = 0; e < 64; e++) dst[e] = row[e] * inv;
}

// ------------- Weff[b][h*64+e][j] = sum_d attn[b,h,d,e] * Wp[h*64+d][j] -----
__global__ void weff_kernel(const float* __restrict__ attn,
                            const float* __restrict__ Wp,
                            float* __restrict__ weff)
{
    int eg = blockIdx.x;
    int b = blockIdx.y;
    int tid = threadIdx.x;
    int h = eg >> 6, e = eg & 63;

    __shared__ float a_s[64];
    if (tid < 64) a_s[tid] = attn[((size_t)(b * NHEAD + h) * 64 + tid) * 64 + e];
    __syncthreads();

    for (int j = tid; j < CC; j += 256) {
        float acc = 0.f;
#pragma unroll
        for (int d = 0; d < 64; d++)
            acc += a_s[d] * Wp[(size_t)(h * 64 + d) * CC + j];
        weff[((size_t)b * CC + eg) * CC + j] = acc;
    }
}

// ------------- fused dwconv3 -> GELU -> dwconv3 -> conv buffer -------------
__global__ void __launch_bounds__(256) dwconv_fused(
    const float* __restrict__ in, const float* __restrict__ w1,
    const float* __restrict__ w2, float* __restrict__ cv)
{
    __shared__ float sin_[20 * 20 * 16];
    __shared__ float t[18 * 18 * 16];
    const int chb = (blockIdx.z & 31) * 16;
    const int b = blockIdx.z >> 5;
    const int x0 = blockIdx.x * 16, y0 = blockIdx.y * 16;
    const int ch = threadIdx.x & 15;
    const int sp = threadIdx.x >> 4;

    for (int p = threadIdx.x; p < 20 * 20 * 16; p += 256) {
        int c2 = p & 15;
        int xx = (p >> 4) % 20;
        int yy = p / (20 * 16);
        int gy = y0 + yy - 2, gx = x0 + xx - 2;
        float v = 0.f;
        if (gy >= 0 && gy < HH && gx >= 0 && gx < WW)
            v = in[(((size_t)b * HH + gy) * WW + gx) * CC + chb + c2];
        sin_[p] = v;
    }
    __syncthreads();

    float wv[9];
#pragma unroll
    for (int k = 0; k < 9; k++) wv[k] = w1[(chb + ch) * 9 + k];

    for (int p = sp; p < 324; p += 16) {
        int ly = p / 18, lx = p - ly * 18;
        int oy = y0 + ly - 1, ox = x0 + lx - 1;
        float val = 0.f;
        if (oy >= 0 && oy < HH && ox >= 0 && ox < WW) {
            float acc = 0.f;
#pragma unroll
            for (int dy = 0; dy < 3; dy++)
#pragma unroll
                for (int dx = 0; dx < 3; dx++)
                    acc += sin_[((ly + dy) * 20 + lx + dx) * 16 + ch] * wv[dy * 3 + dx];
            val = 0.5f * acc * (1.f + erff(acc * 0.70710678118654752f));
        }
        t[p * 16 + ch] = val;
    }
    __syncthreads();

#pragma unroll
    for (int k = 0; k < 9; k++) wv[k] = w2[(chb + ch) * 9 + k];

    for (int p = sp; p < 256; p += 16) {
        int ly = p >> 4, lx = p & 15;
        float acc = 0.f;
#pragma unroll
        for (int dy = 0; dy < 3; dy++)
#pragma unroll
            for (int dx = 0; dx < 3; dx++)
                acc += t[((ly + dy) * 18 + lx + dx) * 16 + ch] * wv[dy * 3 + dx];
        size_t o = (((size_t)b * HH + y0 + ly) * WW + x0 + lx) * CC + chb + ch;
        cv[o] = acc;
    }
}

// ------------- out += conv --------------------------------------------------
__global__ void final_add(float* __restrict__ out, const float* __restrict__ cv)
{
    size_t g = ((size_t)blockIdx.x * 256 + threadIdx.x) * 4;
    float4 a = *(float4*)(out + g);
    float4 b = *(const float4*)(cv + g);
    a.x += b.x; a.y += b.y; a.z += b.z; a.w += b.w;
    *(float4*)(out + g) = a;
}

// ---------------------------------------------------------------------------
extern "C" void kernel_launch(void* const* d_in, const int* in_sizes, int n_in,
                              void* d_out, int out_size)
{
    const float* x    = (const float*)d_in[0];
    const float* illu = (const float*)d_in[1];
    const float* Wq   = (const float*)d_in[2];
    const float* Wk   = (const float*)d_in[3];
    const float* Wv   = (const float*)d_in[4];
    const float* resc = (const float*)d_in[5];
    const float* Wp   = (const float*)d_in[6];
    const float* bp   = (const float*)d_in[7];
    const float* c1w  = (const float*)d_in[8];
    const float* c2w  = (const float*)d_in[9];
    float* out = (float*)d_out;

    float *vinp, *conv, *weff, *nqk, *iq, *ik, *gp, *attn;
    bf16 *xhi, *xlo, *vhi, *vlo, *wThi, *wTlo, *wfhi, *wflo, *qkt;
    cudaGetSymbolAddress((void**)&vinp, g_vinp);
    cudaGetSymbolAddress((void**)&conv, g_conv);
    cudaGetSymbolAddress((void**)&weff, g_weff);
    cudaGetSymbolAddress((void**)&nqk, g_nqk);
    cudaGetSymbolAddress((void**)&iq, g_invq);
    cudaGetSymbolAddress((void**)&ik, g_invk);
    cudaGetSymbolAddress((void**)&gp, g_gpart);
    cudaGetSymbolAddress((void**)&attn, g_attn);
    cudaGetSymbolAddress((void**)&xhi, g_xhi);
    cudaGetSymbolAddress((void**)&xlo, g_xlo);
    cudaGetSymbolAddress((void**)&vhi, g_vhi);
    cudaGetSymbolAddress((void**)&vlo, g_vlo);
    cudaGetSymbolAddress((void**)&wThi, g_wThi);
    cudaGetSymbolAddress((void**)&wTlo, g_wTlo);
    cudaGetSymbolAddress((void**)&wfhi, g_wfhi);
    cudaGetSymbolAddress((void**)&wflo, g_wflo);
    cudaGetSymbolAddress((void**)&qkt, g_qkt);
    bf16* qthi = qkt;
    bf16* kthi = qkt + (size_t)BB * CC * NTOK;

    cudaFuncSetAttribute(gemm_bf<1>, cudaFuncAttributeMaxDynamicSharedMemorySize, GEMM_SMEM);
    cudaFuncSetAttribute(gemm_bf<2>, cudaFuncAttributeMaxDynamicSharedMemorySize, GEMM_SMEM);
    cudaFuncSetAttribute(gemm_qk, cudaFuncAttributeMaxDynamicSharedMemorySize, GEMM1_SMEM);

    // side stream + fork/join events (host objects only; no device allocation)
    cudaStream_t s2;
    cudaStreamCreateWithFlags(&s2, cudaStreamNonBlocking);
    cudaEvent_t evQK, evV, evW, evC;
    cudaEventCreateWithFlags(&evQK, cudaEventDisableTiming);
    cudaEventCreateWithFlags(&evV, cudaEventDisableTiming);
    cudaEventCreateWithFlags(&evW, cudaEventDisableTiming);
    cudaEventCreateWithFlags(&evC, cudaEventDisableTiming);

    // 0) conversions
    cvt_x<<<(int)((size_t)MTOT * CC / (256 * 8)), 256>>>(x, xhi, xlo);
    dim3 tb(32, 8);
    tcvt<<<dim3(8, 16, 1), tb>>>(Wq, wThi, wTlo, CC, 0, 0);
    tcvt<<<dim3(8, 16, 1), tb>>>(Wk, wThi + CC * CC, wTlo + CC * CC, CC, 0, 0);
    tcvt<<<dim3(8, 16, 1), tb>>>(Wv, wThi + 2 * CC * CC, wTlo + 2 * CC * CC, CC, 0, 0);

    // 1) q+k merged 1-term projection (transposed hi + norm partials)
    gemm_qk<<<dim3(CC / 128, MTOT / 128, 2), 256, GEMM1_SMEM>>>(xhi, wThi, qkt, nqk);
    cudaEventRecord(evQK, 0);

    // ---- side stream: attention chain (hidden under v-projection) ----
    cudaStreamWaitEvent(s2, evQK, 0);
    norm_reduce<<<BB, CC, 0, s2>>>(nqk, iq, ik);
    gram_mma<<<dim3(NHEAD, BB, GSPLIT), 256, 0, s2>>>(kthi, qthi, gp);
    softmax_kernel<<<BB * NHEAD, 64, 0, s2>>>(gp, iq, ik, resc, attn);
    weff_kernel<<<dim3(CC, BB), 256, 0, s2>>>(attn, Wp, weff);
    tcvt<<<dim3(8, 16, BB), tb, 0, s2>>>(weff, wfhi, wflo, CC,
        (size_t)CC * CC, (size_t)CC * CC);
    cudaEventRecord(evW, s2);

    // 2) v projection (main stream, 3-term)
    gemm_bf<1><<<dim3(CC / 128, MTOT / 128, 1), 256, GEMM_SMEM>>>(
        xhi, xlo, wThi + 2 * CC * CC, wTlo + 2 * CC * CC,
        nullptr, vinp, vhi, vlo, illu, nullptr, 0, 0);
    cudaEventRecord(evV, 0);

    // ---- side stream: conv branch (hidden under out-gemm) ----
    cudaStreamWaitEvent(s2, evV, 0);
    dwconv_fused<<<dim3(WW / 16, HH / 16, BB * 32), 256, 0, s2>>>(vinp, c1w, c2w, conv);
    cudaEventRecord(evC, s2);

    // 3) out_c = V @ Weff_b + bp (batched, 3-term)
    cudaStreamWaitEvent(0, evW, 0);
    gemm_bf<2><<<dim3(CC / 128, NTOK / 128, BB), 256, GEMM_SMEM>>>(
        vhi, vlo, wfhi, wflo, out, nullptr, nullptr, nullptr, nullptr, bp,
        (size_t)NTOK, (size_t)CC * CC);

    // 4) out += conv
    cudaStreamWaitEvent(0, evC, 0);
    final_add<<<(int)((size_t)MTOT * CC / 1024), 256>>>(out, conv);
}

// round 17
// speedup vs baseline: 2.1214x; 1.0743x over previous
#include <cuda_runtime.h>
#include <cuda_bf16.h>
#include <math.h>
#include <stdint.h>

// Problem constants
#define BB 4
#define HH 128
#define WW 128
#define CC 512
#define NTOK 16384            // H*W
#define NHEAD 8
#define DHEAD 64
#define MTOT (BB*NTOK)        // 65536
#define GSPLIT 8
#define GS_TOT 64

typedef __nv_bfloat16 bf16;

// ---------------- scratch (device globals; no runtime allocation) ----------
static __device__ float g_vinp[(size_t)MTOT * CC];   // raw x@Wv (conv branch)
static __device__ float g_vg[(size_t)MTOT * CC];     // gated v, tf32-rounded
static __device__ float g_conv[(size_t)MTOT * CC];   // conv branch output
static __device__ float g_weff[(size_t)BB * CC * CC];
static __device__ float g_wft[(size_t)BB * CC * CC]; // weff^T, tf32-rounded

static __device__ __align__(16) bf16 g_xhi[(size_t)MTOT * CC];
static __device__ __align__(16) bf16 g_xlo[(size_t)MTOT * CC];
static __device__ __align__(16) bf16 g_wThi[3 * CC * CC];
static __device__ __align__(16) bf16 g_wTlo[3 * CC * CC];
static __device__ __align__(16) bf16 g_qkt[2 * (size_t)BB * CC * NTOK]; // q^T,k^T hi

static __device__ float g_nqk[2 * (size_t)BB * 128 * CC];  // colsumsq partials
static __device__ float g_invq[BB * CC];
static __device__ float g_invk[BB * CC];
static __device__ float g_gpart[(size_t)GS_TOT * BB * NHEAD * DHEAD * DHEAD];
static __device__ float g_attn[(size_t)BB * NHEAD * DHEAD * DHEAD];

// =================== helpers ==============================================
__device__ __forceinline__ uint32_t s2u(const void* p) {
    uint32_t a;
    asm("{ .reg .u64 t; cvta.to.shared.u64 t, %1; cvt.u32.u64 %0, t; }"
        : "=r"(a) : "l"(p));
    return a;
}

// split 2 floats -> packed bf16 hi pair and lo pair (low half = first arg)
__device__ __forceinline__ void cvt2(float a, float b, uint32_t& h, uint32_t& l) {
    uint32_t hp;
    asm("cvt.rn.bf16x2.f32 %0, %1, %2;" : "=r"(hp) : "f"(b), "f"(a));
    float ah = __uint_as_float(hp << 16);
    float bh = __uint_as_float(hp & 0xFFFF0000u);
    float al = a - ah;
    float bl = b - bh;
    uint32_t lp;
    asm("cvt.rn.bf16x2.f32 %0, %1, %2;" : "=r"(lp) : "f"(bl), "f"(al));
    h = hp; l = lp;
}

__device__ __forceinline__ uint32_t packbf(float a, float b) {
    uint32_t hp;
    asm("cvt.rn.bf16x2.f32 %0, %1, %2;" : "=r"(hp) : "f"(b), "f"(a));
    return hp;
}

__device__ __forceinline__ void split1(float f, uint16_t& h, uint16_t& l) {
    uint32_t hp;
    asm("cvt.rn.bf16x2.f32 %0, %1, %2;" : "=r"(hp) : "f"(0.f), "f"(f));
    float hf = __uint_as_float(hp << 16);
    float lf = f - hf;
    uint32_t lp;
    asm("cvt.rn.bf16x2.f32 %0, %1, %2;" : "=r"(lp) : "f"(0.f), "f"(lf));
    h = (uint16_t)hp; l = (uint16_t)lp;
}

// round-to-nearest tf32 (result as fp32 bits with truncated mantissa)
__device__ __forceinline__ float totf32(float f) {
    float r;
    asm("cvt.rna.tf32.f32 %0, %1;" : "=f"(r) : "f"(f));
    return r;
}

__device__ __forceinline__ void ldm_x4(uint32_t* r, uint32_t addr) {
    asm volatile("ldmatrix.sync.aligned.m8n8.x4.shared.b16 {%0,%1,%2,%3}, [%4];"
                 : "=r"(r[0]), "=r"(r[1]), "=r"(r[2]), "=r"(r[3]) : "r"(addr));
}
__device__ __forceinline__ void mma16816(float* c, const uint32_t* a, const uint32_t* b) {
    asm volatile(
        "mma.sync.aligned.m16n8k16.row.col.f32.bf16.bf16.f32 "
        "{%0,%1,%2,%3}, {%4,%5,%6,%7}, {%8,%9}, {%0,%1,%2,%3};"
        : "+f"(c[0]), "+f"(c[1]), "+f"(c[2]), "+f"(c[3])
        : "r"(a[0]), "r"(a[1]), "r"(a[2]), "r"(a[3]), "r"(b[0]), "r"(b[1]));
}
__device__ __forceinline__ void mmatf(float* c, const uint32_t* a, const uint32_t* b) {
    asm volatile(
        "mma.sync.aligned.m16n8k8.row.col.f32.tf32.tf32.f32 "
        "{%0,%1,%2,%3}, {%4,%5,%6,%7}, {%8,%9}, {%0,%1,%2,%3};"
        : "+f"(c[0]), "+f"(c[1]), "+f"(c[2]), "+f"(c[3])
        : "r"(a[0]), "r"(a[1]), "r"(a[2]), "r"(a[3]), "r"(b[0]), "r"(b[1]));
}
__device__ __forceinline__ void cp16(uint32_t dst, const void* src) {
    asm volatile("cp.async.cg.shared.global [%0], [%1], 16;" :: "r"(dst), "l"(src));
}

// =================== conversion kernels ====================================
__global__ void cvt_x(const float* __restrict__ x, bf16* __restrict__ xhi,
                      bf16* __restrict__ xlo)
{
    size_t g = ((size_t)blockIdx.x * 256 + threadIdx.x);
    const float4* p = (const float4*)(x + g * 8);
    float4 a = p[0], b = p[1];
    uint4 h, l;
    cvt2(a.x, a.y, h.x, l.x); cvt2(a.z, a.w, h.y, l.y);
    cvt2(b.x, b.y, h.z, l.z); cvt2(b.z, b.w, h.w, l.w);
    ((uint4*)xhi)[g] = h;
    ((uint4*)xlo)[g] = l;
}

// transpose + convert: src fp32 [R][512] (batched) -> dst bf16 [512][R] hi/lo
__global__ void tcvt(const float* __restrict__ src, bf16* __restrict__ dhi,
                     bf16* __restrict__ dlo, int R, size_t sStride, size_t dStride)
{
    __shared__ uint16_t shh[32][65];
    __shared__ uint16_t shl[32][65];
    int z = blockIdx.z;
    const float* s = src + (size_t)z * sStride;
    int c = blockIdx.y * 32 + threadIdx.x;
    int nb = blockIdx.x * 64;
#pragma unroll
    for (int i = 0; i < 8; i++) {
        int n = threadIdx.y + i * 8;
        float f = s[(size_t)(nb + n) * CC + c];
        uint16_t h, l;
        split1(f, h, l);
        shh[threadIdx.x][n] = h;
        shl[threadIdx.x][n] = l;
    }
    __syncthreads();
#pragma unroll
    for (int i = 0; i < 4; i++) {
        int cl = threadIdx.y + i * 8;
        int row = blockIdx.y * 32 + cl;
        size_t u32idx = ((size_t)row * R + nb) >> 1;
        uint32_t h = (uint32_t)shh[cl][threadIdx.x * 2] |
                     ((uint32_t)shh[cl][threadIdx.x * 2 + 1] << 16);
        uint32_t l = (uint32_t)shl[cl][threadIdx.x * 2] |
                     ((uint32_t)shl[cl][threadIdx.x * 2 + 1] << 16);
        ((uint32_t*)(dhi + (size_t)z * dStride))[u32idx + threadIdx.x] = h;
        ((uint32_t*)(dlo + (size_t)z * dStride))[u32idx + threadIdx.x] = l;
    }
}

// transpose + tf32-round: weff [b][e][j] fp32 -> wft [b][j][e] fp32
__global__ void transpose_rna(const float* __restrict__ src, float* __restrict__ dst)
{
    __shared__ float t[32][33];
    size_t bo = (size_t)blockIdx.z * (CC * CC);
    int x = blockIdx.x * 32 + threadIdx.x;
    int y0 = blockIdx.y * 32;
    for (int j = threadIdx.y; j < 32; j += 8)
        t[j][threadIdx.x] = src[bo + (size_t)(y0 + j) * CC + x];
    __syncthreads();
    int xo = blockIdx.y * 32 + threadIdx.x;
    int yo0 = blockIdx.x * 32;
    for (int j = threadIdx.y; j < 32; j += 8)
        dst[bo + (size_t)(yo0 + j) * CC + xo] = totf32(t[threadIdx.x][j]);
}

// =================== pipelined bf16 GEMM (3-term, V projection) ============
#define KCH 32
#define ROWB 80
#define MATB (128 * ROWB)        // 10240
#define STAGEB (4 * MATB)        // 40960
#define GEMM_SMEM (2 * STAGEB)   // 81920

__device__ __forceinline__ void stage_issue(
    uint32_t sb, int tid,
    const bf16* aHi, const bf16* aLo, const bf16* bHi, const bf16* bLo)
{
    const bf16* g[4] = {aHi, aLo, bHi, bLo};
#pragma unroll
    for (int m = 0; m < 4; m++) {
#pragma unroll
        for (int it = 0; it < 2; it++) {
            int u = tid + it * 256;
            int r = u >> 2, seg = u & 3;
            cp16(sb + m * MATB + r * ROWB + seg * 16,
                 g[m] + (size_t)r * CC + seg * 8);
        }
    }
    asm volatile("cp.async.commit_group;" ::: "memory");
}

__global__ void __launch_bounds__(256, 2) gemm_v3(
    const bf16* __restrict__ Ahi, const bf16* __restrict__ Alo,
    const bf16* __restrict__ Bhi, const bf16* __restrict__ Blo,
    float* __restrict__ C2, float* __restrict__ Vg,
    const float* __restrict__ illu)
{
    extern __shared__ char smem[];
    const uint32_t sb0 = s2u(smem);
    const int tid = threadIdx.x;
    const int wid = tid >> 5, lane = tid & 31;
    const int wm = wid & 1, wn = wid >> 1;

    const size_t row0 = (size_t)blockIdx.y * 128;
    const int n0 = blockIdx.x * 128;
    const size_t boff = (size_t)n0 * CC;

    float acc[4][4][4];
#pragma unroll
    for (int i = 0; i < 4; i++)
#pragma unroll
        for (int j = 0; j < 4; j++)
#pragma unroll
            for (int t = 0; t < 4; t++) acc[i][j][t] = 0.f;

    const int a_row = wm * 64 + (lane & 15);
    const int a_koff = (lane >> 4) * 16;
    const int b_row4 = wn * 32 + ((lane >> 4) & 1) * 8 + (lane & 7);
    const int b_koff4 = ((lane >> 3) & 1) * 16;

    stage_issue(sb0, tid, Ahi + row0 * CC, Alo + row0 * CC, Bhi + boff, Blo + boff);
    stage_issue(sb0 + STAGEB, tid, Ahi + row0 * CC + KCH, Alo + row0 * CC + KCH,
                Bhi + boff + KCH, Blo + boff + KCH);

    for (int ch = 0; ch < 16; ch++) {
        const int cur = ch & 1;
        if (ch < 15) asm volatile("cp.async.wait_group 1;" ::: "memory");
        else         asm volatile("cp.async.wait_group 0;" ::: "memory");
        __syncthreads();

        const uint32_t base = sb0 + cur * STAGEB;
        const uint32_t aHs = base, aLs = base + MATB;
        const uint32_t bHs = base + 2 * MATB, bLs = base + 3 * MATB;
#pragma unroll
        for (int ks = 0; ks < 2; ks++) {
            const int kb = ks * 32;
            uint32_t ah[4][4], al[4][4], bh[4][2], bl[4][2];
#pragma unroll
            for (int i = 0; i < 4; i++) {
                uint32_t ra = (a_row + i * 16) * ROWB + kb + a_koff;
                ldm_x4(ah[i], aHs + ra);
                ldm_x4(al[i], aLs + ra);
            }
#pragma unroll
            for (int jp = 0; jp < 2; jp++) {
                uint32_t rb = (b_row4 + jp * 16) * ROWB + kb + b_koff4;
                uint32_t t4[4];
                ldm_x4(t4, bHs + rb);
                bh[jp * 2][0] = t4[0]; bh[jp * 2][1] = t4[1];
                bh[jp * 2 + 1][0] = t4[2]; bh[jp * 2 + 1][1] = t4[3];
                ldm_x4(t4, bLs + rb);
                bl[jp * 2][0] = t4[0]; bl[jp * 2][1] = t4[1];
                bl[jp * 2 + 1][0] = t4[2]; bl[jp * 2 + 1][1] = t4[3];
            }
#pragma unroll
            for (int i = 0; i < 4; i++)
#pragma unroll
                for (int j = 0; j < 4; j++) {
                    mma16816(acc[i][j], ah[i], bh[j]);
                    mma16816(acc[i][j], ah[i], bl[j]);
                    mma16816(acc[i][j], al[i], bh[j]);
                }
        }
        __syncthreads();
        if (ch + 2 < 16) {
            const int k0 = (ch + 2) * KCH;
            stage_issue(base, tid, Ahi + row0 * CC + k0, Alo + row0 * CC + k0,
                        Bhi + boff + k0, Blo + boff + k0);
        }
    }

    const int mrow = wm * 64 + (lane >> 2);
    const int mcol = wn * 32 + (lane & 3) * 2;
#pragma unroll
    for (int i = 0; i < 4; i++) {
#pragma unroll
        for (int half = 0; half < 2; half++) {
            size_t r = row0 + mrow + i * 16 + half * 8;
            size_t base = r * CC + n0 + mcol;
#pragma unroll
            for (int j = 0; j < 4; j++) {
                float2 v2;
                v2.x = acc[i][j][half * 2 + 0];
                v2.y = acc[i][j][half * 2 + 1];
                size_t off = base + j * 8;
                float2 iv = *(const float2*)(illu + off);
                *(float2*)(C2 + off) = v2;
                float2 gv;
                gv.x = totf32(v2.x * iv.x);
                gv.y = totf32(v2.y * iv.y);
                *(float2*)(Vg + off) = gv;
            }
        }
    }
}

// =================== tf32 out-GEMM: C = Vg @ Wft^T + bias ==================
// A, B fp32 (tf32-rounded). CTA 128x128, 8 warps 64x32, k-chunk 32,
// m16n8k8 tf32 MMA (1 term), 2-stage cp.async, 2 CTAs/SM.
#define TROWF 36                      // floats per smem row (32 + 4 pad)
#define TROWB (TROWF * 4)             // 144 bytes
#define TMATB (128 * TROWB)           // 18432
#define TSTAGEB (2 * TMATB)           // 36864
#define OUT_SMEM (2 * TSTAGEB)        // 73728

__device__ __forceinline__ void stage_issue_t(
    uint32_t sb, int tid, const float* A, const float* B)
{
    const float* g[2] = {A, B};
#pragma unroll
    for (int m = 0; m < 2; m++) {
#pragma unroll
        for (int it = 0; it < 4; it++) {
            int u = tid + it * 256;
            int r = u >> 3, seg = u & 7;
            cp16(sb + m * TMATB + r * TROWB + seg * 16,
                 g[m] + (size_t)r * CC + seg * 4);
        }
    }
    asm volatile("cp.async.commit_group;" ::: "memory");
}

__global__ void __launch_bounds__(256, 2) gemm_out_tf32(
    const float* __restrict__ A, const float* __restrict__ B,
    float* __restrict__ C, const float* __restrict__ bias,
    size_t zRow, size_t sB)
{
    extern __shared__ char smem[];
    const uint32_t sb0 = s2u(smem);
    const int tid = threadIdx.x;
    const int wid = tid >> 5, lane = tid & 31;
    const int wm = wid & 1, wn = wid >> 1;
    const int g = lane >> 2, c = lane & 3;

    const size_t row0 = (size_t)blockIdx.y * 128 + (size_t)blockIdx.z * zRow;
    const int n0 = blockIdx.x * 128;
    const size_t boff = (size_t)blockIdx.z * sB + (size_t)n0 * CC;

    float acc[4][4][4];
#pragma unroll
    for (int i = 0; i < 4; i++)
#pragma unroll
        for (int j = 0; j < 4; j++)
#pragma unroll
            for (int t = 0; t < 4; t++) acc[i][j][t] = 0.f;

    stage_issue_t(sb0, tid, A + row0 * CC, B + boff);
    stage_issue_t(sb0 + TSTAGEB, tid, A + row0 * CC + KCH, B + boff + KCH);

    for (int ch = 0; ch < 16; ch++) {
        const int cur = ch & 1;
        if (ch < 15) asm volatile("cp.async.wait_group 1;" ::: "memory");
        else         asm volatile("cp.async.wait_group 0;" ::: "memory");
        __syncthreads();

        const float* As = (const float*)(smem + cur * TSTAGEB);
        const float* Bs = As + (TMATB / 4);
#pragma unroll
        for (int s = 0; s < 4; s++) {
            uint32_t af[4][4], bf[4][2];
#pragma unroll
            for (int mt = 0; mt < 4; mt++) {
                const float* pa = As + (wm * 64 + mt * 16 + g) * TROWF + s * 8 + c;
                af[mt][0] = __float_as_uint(pa[0]);
                af[mt][1] = __float_as_uint(pa[8 * TROWF]);
                af[mt][2] = __float_as_uint(pa[4]);
                af[mt][3] = __float_as_uint(pa[8 * TROWF + 4]);
            }
#pragma unroll
            for (int nt = 0; nt < 4; nt++) {
                const float* pb = Bs + (wn * 32 + nt * 8 + g) * TROWF + s * 8 + c;
                bf[nt][0] = __float_as_uint(pb[0]);
                bf[nt][1] = __float_as_uint(pb[4]);
            }
#pragma unroll
            for (int mt = 0; mt < 4; mt++)
#pragma unroll
                for (int nt = 0; nt < 4; nt++)
                    mmatf(acc[mt][nt], af[mt], bf[nt]);
        }
        __syncthreads();
        if (ch + 2 < 16) {
            const int k0 = (ch + 2) * KCH;
            stage_issue_t(sb0 + cur * TSTAGEB, tid, A + row0 * CC + k0, B + boff + k0);
        }
    }

    const int mrow = wm * 64 + g;
    const int mcol = wn * 32 + c * 2;
#pragma unroll
    for (int i = 0; i < 4; i++) {
#pragma unroll
        for (int half = 0; half < 2; half++) {
            size_t r = row0 + mrow + i * 16 + half * 8;
            size_t base = r * CC + n0 + mcol;
#pragma unroll
            for (int j = 0; j < 4; j++) {
                float2 v2;
                v2.x = acc[i][j][half * 2 + 0];
                v2.y = acc[i][j][half * 2 + 1];
                size_t off = base + j * 8;
                float2 bv = *(const float2*)(bias + n0 + mcol + j * 8);
                v2.x += bv.x; v2.y += bv.y;
                *(float2*)(C + off) = v2;
            }
        }
    }
}

// =================== 1-term bf16 GEMM for Q/K merged (hi-only) =============
#define STAGE1B (2 * MATB)         // 20480
#define GEMM1_SMEM (2 * STAGE1B)   // 40960

__device__ __forceinline__ void stage_issue1(
    uint32_t sb, int tid, const bf16* aHi, const bf16* bHi)
{
    const bf16* g[2] = {aHi, bHi};
#pragma unroll
    for (int m = 0; m < 2; m++) {
#pragma unroll
        for (int it = 0; it < 2; it++) {
            int u = tid + it * 256;
            int r = u >> 2, seg = u & 3;
            cp16(sb + m * MATB + r * ROWB + seg * 16,
                 g[m] + (size_t)r * CC + seg * 8);
        }
    }
    asm volatile("cp.async.commit_group;" ::: "memory");
}

__global__ void __launch_bounds__(256, 2) gemm_qk(
    const bf16* __restrict__ Ahi, const bf16* __restrict__ WThi,
    bf16* __restrict__ Oqk, float* __restrict__ npart)
{
    extern __shared__ char smem[];
    const uint32_t sb0 = s2u(smem);
    const int tid = threadIdx.x;
    const int wid = tid >> 5, lane = tid & 31;
    const int wm = wid & 1, wn = wid >> 1;
    const int z = blockIdx.z;

    const bf16* Bhi = WThi + (size_t)z * CC * CC;
    bf16* Ohi = Oqk + (size_t)z * BB * CC * NTOK;
    float* np = npart + (size_t)z * BB * 128 * CC;

    const size_t row0 = (size_t)blockIdx.y * 128;
    const int n0 = blockIdx.x * 128;
    const size_t boff = (size_t)n0 * CC;

    float acc[4][4][4];
#pragma unroll
    for (int i = 0; i < 4; i++)
#pragma unroll
        for (int j = 0; j < 4; j++)
#pragma unroll
            for (int t = 0; t < 4; t++) acc[i][j][t] = 0.f;

    const int a_row = wm * 64 + (lane & 15);
    const int a_koff = (lane >> 4) * 16;
    const int b_row4 = wn * 32 + ((lane >> 4) & 1) * 8 + (lane & 7);
    const int b_koff4 = ((lane >> 3) & 1) * 16;

    stage_issue1(sb0, tid, Ahi + row0 * CC, Bhi + boff);
    stage_issue1(sb0 + STAGE1B, tid, Ahi + row0 * CC + KCH, Bhi + boff + KCH);

    for (int ch = 0; ch < 16; ch++) {
        const int cur = ch & 1;
        if (ch < 15) asm volatile("cp.async.wait_group 1;" ::: "memory");
        else         asm volatile("cp.async.wait_group 0;" ::: "memory");
        __syncthreads();

        const uint32_t base = sb0 + cur * STAGE1B;
        const uint32_t aHs = base, bHs = base + MATB;
#pragma unroll
        for (int ks = 0; ks < 2; ks++) {
            const int kb = ks * 32;
            uint32_t ah[4][4], bh[4][2];
#pragma unroll
            for (int i = 0; i < 4; i++) {
                uint32_t ra = (a_row + i * 16) * ROWB + kb + a_koff;
                ldm_x4(ah[i], aHs + ra);
            }
#pragma unroll
            for (int jp = 0; jp < 2; jp++) {
                uint32_t rb = (b_row4 + jp * 16) * ROWB + kb + b_koff4;
                uint32_t t4[4];
                ldm_x4(t4, bHs + rb);
                bh[jp * 2][0] = t4[0]; bh[jp * 2][1] = t4[1];
                bh[jp * 2 + 1][0] = t4[2]; bh[jp * 2 + 1][1] = t4[3];
            }
#pragma unroll
            for (int i = 0; i < 4; i++)
#pragma unroll
                for (int j = 0; j < 4; j++)
                    mma16816(acc[i][j], ah[i], bh[j]);
        }
        __syncthreads();
        if (ch + 2 < 16) {
            const int k0 = (ch + 2) * KCH;
            stage_issue1(base, tid, Ahi + row0 * CC + k0, Bhi + boff + k0);
        }
    }

    // ---- epilogue 1: transposed bf16 hi output via smem transpose ----
    const int mrow = wm * 64 + (lane >> 2);
    const int mcol = wn * 32 + (lane & 3) * 2;

    float ss[8];
#pragma unroll
    for (int t = 0; t < 8; t++) ss[t] = 0.f;

    uint16_t* shh = (uint16_t*)smem;
    __syncthreads();
#pragma unroll
    for (int i = 0; i < 4; i++)
#pragma unroll
        for (int half = 0; half < 2; half++) {
            int row = mrow + i * 16 + half * 8;
#pragma unroll
            for (int j = 0; j < 4; j++) {
                int col = mcol + j * 8;
                float a0 = acc[i][j][half * 2 + 0];
                float a1 = acc[i][j][half * 2 + 1];
                ss[j * 2 + 0] += a0 * a0;
                ss[j * 2 + 1] += a1 * a1;
                uint32_t h = packbf(a0, a1);
                shh[col * 130 + row] = (uint16_t)h;
                shh[(col + 1) * 130 + row] = (uint16_t)(h >> 16);
            }
        }
    __syncthreads();
    const int b = (int)(blockIdx.y >> 7);
    const size_t nl0 = (size_t)(blockIdx.y & 127) * 128;
    uint32_t* dh = (uint32_t*)Ohi;
#pragma unroll
    for (int it = 0; it < 32; it++) {
        int cc2 = it * 4 + (tid >> 6);
        int w = tid & 63;
        uint32_t hv = *(uint32_t*)(&shh[cc2 * 130 + 2 * w]);
        size_t idx = ((((size_t)b * CC + n0 + cc2) * NTOK + nl0) >> 1) + w;
        dh[idx] = hv;
    }

    // ---- epilogue 2: per-CTA column sumsq partials ----
    __syncthreads();
    float* sred = (float*)smem;
#pragma unroll
    for (int j = 0; j < 4; j++)
#pragma unroll
        for (int par = 0; par < 2; par++) {
            int col = mcol + j * 8 + par;
            sred[col * 16 + wm * 8 + (lane >> 2)] = ss[j * 2 + par];
        }
    __syncthreads();
    if (tid < 128) {
        float s = 0.f;
#pragma unroll
        for (int t = 0; t < 16; t++) s += sred[tid * 16 + t];
        int rb = (int)(blockIdx.y & 127);
        np[((size_t)(b * 128 + rb)) * CC + n0 + tid] = s;
    }
}

// ------------- reduce column-sumsq partials -> inverse norms ---------------
__global__ void norm_reduce(const float* __restrict__ nqk,
                            float* __restrict__ iq, float* __restrict__ ik)
{
    const int b = blockIdx.x;
    const int c = threadIdx.x;
    const float* nq = nqk;
    const float* nk = nqk + (size_t)BB * 128 * CC;
    float sq = 0.f, sk = 0.f;
    for (int rb = 0; rb < 128; rb++) {
        sq += nq[((size_t)(b * 128 + rb)) * CC + c];
        sk += nk[((size_t)(b * 128 + rb)) * CC + c];
    }
    iq[b * CC + c] = 1.f / fmaxf(sqrtf(sq), 1e-12f);
    ik[b * CC + c] = 1.f / fmaxf(sqrtf(sk), 1e-12f);
}

// ------------- Gram via mma with direct-LDG fragments (1-term hi) ----------
__global__ void __launch_bounds__(256) gram_mma(
    const bf16* __restrict__ KThi, const bf16* __restrict__ QThi,
    float* __restrict__ part)
{
    const int h = blockIdx.x, b = blockIdx.y, s = blockIdx.z;
    const int wid = threadIdx.x >> 5, lane = threadIdx.x & 31;
    const int nbase = s * (NTOK / GSPLIT) + wid * 256;

    const size_t rowbase = ((size_t)b * CC + h * DHEAD) * NTOK;
    const bf16* Kh = KThi + rowbase;
    const bf16* Qh = QThi + rowbase;

    float acc[4][8][4];
#pragma unroll
    for (int i = 0; i < 4; i++)
#pragma unroll
        for (int j = 0; j < 8; j++)
#pragma unroll
            for (int t = 0; t < 4; t++) acc[i][j][t] = 0.f;

    const int rsel = lane >> 2;
    const int csel = (lane & 3) * 2;

    for (int step = 0; step < 16; step++) {
        const int nb = nbase + step * 16 + csel;
        uint32_t ah[4][4];
#pragma unroll
        for (int mt = 0; mt < 4; mt++) {
            const size_t r0 = (size_t)(mt * 16 + rsel) * NTOK;
            const size_t r8 = r0 + 8 * NTOK;
            ah[mt][0] = *(const uint32_t*)(Kh + r0 + nb);
            ah[mt][1] = *(const uint32_t*)(Kh + r8 + nb);
            ah[mt][2] = *(const uint32_t*)(Kh + r0 + nb + 8);
            ah[mt][3] = *(const uint32_t*)(Kh + r8 + nb + 8);
        }
#pragma unroll
        for (int nt = 0; nt < 8; nt++) {
            const size_t q0 = (size_t)(nt * 8 + rsel) * NTOK;
            uint32_t bh[2];
            bh[0] = *(const uint32_t*)(Qh + q0 + nb);
            bh[1] = *(const uint32_t*)(Qh + q0 + nb + 8);
#pragma unroll
            for (int mt = 0; mt < 4; mt++)
                mma16816(acc[mt][nt], ah[mt], bh);
        }
    }

    const int sp = s * 8 + wid;
    float* dst = part + (((size_t)sp * BB + b) * NHEAD + h) * 4096;
#pragma unroll
    for (int mt = 0; mt < 4; mt++)
#pragma unroll
        for (int nt = 0; nt < 8; nt++) {
            int r = mt * 16 + rsel, c = nt * 8 + csel;
            dst[r * 64 + c]           = acc[mt][nt][0];
            dst[r * 64 + c + 1]       = acc[mt][nt][1];
            dst[(r + 8) * 64 + c]     = acc[mt][nt][2];
            dst[(r + 8) * 64 + c + 1] = acc[mt][nt][3];
        }
}

// ------------- softmax over e ----------------------------------------------
__global__ void softmax_kernel(const float* __restrict__ part,
                               const float* __restrict__ iq,
                               const float* __restrict__ ik,
                               const float* __restrict__ rescale,
                               float* __restrict__ attn)
{
    int bh = blockIdx.x;
    int b = bh / NHEAD, h = bh % NHEAD;
    int d = threadIdx.x;

    __shared__ float iq_s[64];
    iq_s[d] = iq[b * CC + h * DHEAD + d];
    float ik_d = ik[b * CC + h * DHEAD + d];
    float resc = rescale[h];
    __syncthreads();

    float row[64];
#pragma unroll
    for (int e = 0; e < 64; e++) row[e] = 0.f;
    for (int sp = 0; sp < GS_TOT; sp++) {
        const float* p = part + (((size_t)sp * BB + b) * NHEAD + h) * 4096 + d * 64;
#pragma unroll 8
        for (int e = 0; e < 64; e++) row[e] += p[e];
    }
    float m = -1e30f;
#pragma unroll
    for (int e = 0; e < 64; e++) {
        row[e] = row[e] * ik_d * iq_s[e] * resc;
        m = fmaxf(m, row[e]);
    }
    float sum = 0.f;
#pragma unroll
    for (int e = 0; e < 64; e++) {
        row[e] = __expf(row[e] - m);
        sum += row[e];
    }
    float inv = 1.f / sum;
    float* dst = attn + ((size_t)(b * NHEAD + h)) * 4096 + d * 64;
#pragma unroll
    for (int e = 0; e < 64; e++) dst[e] = row[e] * inv;
}

// ------------- Weff[b][h*64+e][j] = sum_d attn[b,h,d,e] * Wp[h*64+d][j] -----
__global__ void weff_kernel(const float* __restrict__ attn,
                            const float* __restrict__ Wp,
                            float* __restrict__ weff)
{
    int eg = blockIdx.x;
    int b = blockIdx.y;
    int tid = threadIdx.x;
    int h = eg >> 6, e = eg & 63;

    __shared__ float a_s[64];
    if (tid < 64) a_s[tid] = attn[((size_t)(b * NHEAD + h) * 64 + tid) * 64 + e];
    __syncthreads();

    for (int j = tid; j < CC; j += 256) {
        float acc = 0.f;
#pragma unroll
        for (int d = 0; d < 64; d++)
            acc += a_s[d] * Wp[(size_t)(h * 64 + d) * CC + j];
        weff[((size_t)b * CC + eg) * CC + j] = acc;
    }
}

// ------------- fused dwconv3 -> GELU -> dwconv3 -> conv buffer -------------
__global__ void __launch_bounds__(256) dwconv_fused(
    const float* __restrict__ in, const float* __restrict__ w1,
    const float* __restrict__ w2, float* __restrict__ cv)
{
    __shared__ float sin_[20 * 20 * 16];
    __shared__ float t[18 * 18 * 16];
    const int chb = (blockIdx.z & 31) * 16;
    const int b = blockIdx.z >> 5;
    const int x0 = blockIdx.x * 16, y0 = blockIdx.y * 16;
    const int ch = threadIdx.x & 15;
    const int sp = threadIdx.x >> 4;

    for (int p = threadIdx.x; p < 20 * 20 * 16; p += 256) {
        int c2 = p & 15;
        int xx = (p >> 4) % 20;
        int yy = p / (20 * 16);
        int gy = y0 + yy - 2, gx = x0 + xx - 2;
        float v = 0.f;
        if (gy >= 0 && gy < HH && gx >= 0 && gx < WW)
            v = in[(((size_t)b * HH + gy) * WW + gx) * CC + chb + c2];
        sin_[p] = v;
    }
    __syncthreads();

    float wv[9];
#pragma unroll
    for (int k = 0; k < 9; k++) wv[k] = w1[(chb + ch) * 9 + k];

    for (int p = sp; p < 324; p += 16) {
        int ly = p / 18, lx = p - ly * 18;
        int oy = y0 + ly - 1, ox = x0 + lx - 1;
        float val = 0.f;
        if (oy >= 0 && oy < HH && ox >= 0 && ox < WW) {
            float acc = 0.f;
#pragma unroll
            for (int dy = 0; dy < 3; dy++)
#pragma unroll
                for (int dx = 0; dx < 3; dx++)
                    acc += sin_[((ly + dy) * 20 + lx + dx) * 16 + ch] * wv[dy * 3 + dx];
            val = 0.5f * acc * (1.f + erff(acc * 0.70710678118654752f));
        }
        t[p * 16 + ch] = val;
    }
    __syncthreads();

#pragma unroll
    for (int k = 0; k < 9; k++) wv[k] = w2[(chb + ch) * 9 + k];

    for (int p = sp; p < 256; p += 16) {
        int ly = p >> 4, lx = p & 15;
        float acc = 0.f;
#pragma unroll
        for (int dy = 0; dy < 3; dy++)
#pragma unroll
            for (int dx = 0; dx < 3; dx++)
                acc += t[((ly + dy) * 18 + lx + dx) * 16 + ch] * wv[dy * 3 + dx];
        size_t o = (((size_t)b * HH + y0 + ly) * WW + x0 + lx) * CC + chb + ch;
        cv[o] = acc;
    }
}

// ------------- out += conv --------------------------------------------------
__global__ void final_add(float* __restrict__ out, const float* __restrict__ cv)
{
    size_t g = ((size_t)blockIdx.x * 256 + threadIdx.x) * 4;
    float4 a = *(float4*)(out + g);
    float4 b = *(const float4*)(cv + g);
    a.x += b.x; a.y += b.y; a.z += b.z; a.w += b.w;
    *(float4*)(out + g) = a;
}

// tiny root kernel so the side stream can fork off a captured node
__global__ void noop_kernel() {}

// ---------------------------------------------------------------------------
extern "C" void kernel_launch(void* const* d_in, const int* in_sizes, int n_in,
                              void* d_out, int out_size)
{
    const float* x    = (const float*)d_in[0];
    const float* illu = (const float*)d_in[1];
    const float* Wq   = (const float*)d_in[2];
    const float* Wk   = (const float*)d_in[3];
    const float* Wv   = (const float*)d_in[4];
    const float* resc = (const float*)d_in[5];
    const float* Wp   = (const float*)d_in[6];
    const float* bp   = (const float*)d_in[7];
    const float* c1w  = (const float*)d_in[8];
    const float* c2w  = (const float*)d_in[9];
    float* out = (float*)d_out;

    float *vinp, *vg, *conv, *weff, *wft, *nqk, *iq, *ik, *gp, *attn;
    bf16 *xhi, *xlo, *wThi, *wTlo, *qkt;
    cudaGetSymbolAddress((void**)&vinp, g_vinp);
    cudaGetSymbolAddress((void**)&vg, g_vg);
    cudaGetSymbolAddress((void**)&conv, g_conv);
    cudaGetSymbolAddress((void**)&weff, g_weff);
    cudaGetSymbolAddress((void**)&wft, g_wft);
    cudaGetSymbolAddress((void**)&nqk, g_nqk);
    cudaGetSymbolAddress((void**)&iq, g_invq);
    cudaGetSymbolAddress((void**)&ik, g_invk);
    cudaGetSymbolAddress((void**)&gp, g_gpart);
    cudaGetSymbolAddress((void**)&attn, g_attn);
    cudaGetSymbolAddress((void**)&xhi, g_xhi);
    cudaGetSymbolAddress((void**)&xlo, g_xlo);
    cudaGetSymbolAddress((void**)&wThi, g_wThi);
    cudaGetSymbolAddress((void**)&wTlo, g_wTlo);
    cudaGetSymbolAddress((void**)&qkt, g_qkt);
    bf16* qthi = qkt;
    bf16* kthi = qkt + (size_t)BB * CC * NTOK;

    cudaFuncSetAttribute(gemm_v3, cudaFuncAttributeMaxDynamicSharedMemorySize, GEMM_SMEM);
    cudaFuncSetAttribute(gemm_out_tf32, cudaFuncAttributeMaxDynamicSharedMemorySize, OUT_SMEM);
    cudaFuncSetAttribute(gemm_qk, cudaFuncAttributeMaxDynamicSharedMemorySize, GEMM1_SMEM);

    cudaStream_t s2;
    cudaStreamCreateWithFlags(&s2, cudaStreamNonBlocking);
    cudaEvent_t evRoot, evQK, evV, evW, evC, evWc;
    cudaEventCreateWithFlags(&evRoot, cudaEventDisableTiming);
    cudaEventCreateWithFlags(&evQK, cudaEventDisableTiming);
    cudaEventCreateWithFlags(&evV, cudaEventDisableTiming);
    cudaEventCreateWithFlags(&evW, cudaEventDisableTiming);
    cudaEventCreateWithFlags(&evC, cudaEventDisableTiming);
    cudaEventCreateWithFlags(&evWc, cudaEventDisableTiming);

    // 0) root node in the capture-origin stream, then legally fork s2 from it
    noop_kernel<<<1, 32>>>();
    cudaEventRecord(evRoot, 0);
    cudaStreamWaitEvent(s2, evRoot, 0);

    // weights converted on side stream, x on main (concurrent)
    dim3 tb(32, 8);
    tcvt<<<dim3(8, 16, 1), tb, 0, s2>>>(Wq, wThi, wTlo, CC, 0, 0);
    tcvt<<<dim3(8, 16, 1), tb, 0, s2>>>(Wk, wThi + CC * CC, wTlo + CC * CC, CC, 0, 0);
    tcvt<<<dim3(8, 16, 1), tb, 0, s2>>>(Wv, wThi + 2 * CC * CC, wTlo + 2 * CC * CC, CC, 0, 0);
    cudaEventRecord(evWc, s2);
    cvt_x<<<(int)((size_t)MTOT * CC / (256 * 8)), 256>>>(x, xhi, xlo);
    cudaStreamWaitEvent(0, evWc, 0);

    // 1) q+k merged 1-term projection (transposed hi + norm partials)
    gemm_qk<<<dim3(CC / 128, MTOT / 128, 2), 256, GEMM1_SMEM>>>(xhi, wThi, qkt, nqk);
    cudaEventRecord(evQK, 0);

    // ---- side stream: attention chain (under v-projection) ----
    cudaStreamWaitEvent(s2, evQK, 0);
    norm_reduce<<<BB, CC, 0, s2>>>(nqk, iq, ik);
    gram_mma<<<dim3(NHEAD, BB, GSPLIT), 256, 0, s2>>>(kthi, qthi, gp);
    softmax_kernel<<<BB * NHEAD, 64, 0, s2>>>(gp, iq, ik, resc, attn);
    weff_kernel<<<dim3(CC, BB), 256, 0, s2>>>(attn, Wp, weff);
    transpose_rna<<<dim3(16, 16, BB), tb, 0, s2>>>(weff, wft);
    cudaEventRecord(evW, s2);

    // 2) v projection (main stream, 3-term; epilogue emits raw + gated-tf32)
    gemm_v3<<<dim3(CC / 128, MTOT / 128, 1), 256, GEMM_SMEM>>>(
        xhi, xlo, wThi + 2 * CC * CC, wTlo + 2 * CC * CC, vinp, vg, illu);
    cudaEventRecord(evV, 0);

    // ---- side stream: conv branch (under out-gemm) ----
    cudaStreamWaitEvent(s2, evV, 0);
    dwconv_fused<<<dim3(WW / 16, HH / 16, BB * 32), 256, 0, s2>>>(vinp, c1w, c2w, conv);
    cudaEventRecord(evC, s2);

    // 3) out_c = Vg @ Wft^T + bp (batched, tf32 1-term)
    cudaStreamWaitEvent(0, evW, 0);
    gemm_out_tf32<<<dim3(CC / 128, NTOK / 128, BB), 256, OUT_SMEM>>>(
        vg, wft, out, bp, (size_t)NTOK, (size_t)CC * CC);

    // 4) out += conv
    cudaStreamWaitEvent(0, evC, 0);
    final_add<<<(int)((size_t)MTOT * CC / 1024), 256>>>(out, conv);
}